// round 6
// baseline (speedup 1.0000x reference)
#include <cuda_runtime.h>
#include <math.h>

#define C_DIM  512
#define PIX    4096          // H*W = 64*64
#define BATCH  2
#define M_TOT  (BATCH * PIX) // 8192
#define NGROUP 32
#define CPG    16            // channels per group
#define GN_N   65536.0f      // PIX * CPG elements per (b,g)

// ---------------- scratch (device globals; no runtime allocation) ----------
__device__ float g_xn[(size_t)M_TOT * C_DIM];
__device__ float g_q [(size_t)M_TOT * C_DIM];
__device__ float g_k [(size_t)M_TOT * C_DIM];
__device__ float g_v [(size_t)M_TOT * C_DIM];
__device__ float g_o [(size_t)M_TOT * C_DIM];
__device__ float g_s [(size_t)BATCH * PIX * PIX];   // attention scores/probs

// ---------------- GroupNorm: one block per (batch, group) ------------------
__global__ void groupnorm_kernel(const float* __restrict__ x,
                                 const float* __restrict__ gamma,
                                 const float* __restrict__ beta,
                                 float* __restrict__ xn) {
    const int b = blockIdx.x >> 5;
    const int g = blockIdx.x & 31;
    const float* xb = x  + (size_t)b * PIX * C_DIM + g * CPG;
    float*       ob = xn + (size_t)b * PIX * C_DIM + g * CPG;
    const int tid = threadIdx.x;

    float sum = 0.f, sq = 0.f;
    for (int p = tid; p < PIX; p += 256) {
        const float4* ptr = (const float4*)(xb + (size_t)p * C_DIM);
        #pragma unroll
        for (int j = 0; j < 4; j++) {
            float4 v = ptr[j];
            sum += v.x + v.y + v.z + v.w;
            sq  += v.x*v.x + v.y*v.y + v.z*v.z + v.w*v.w;
        }
    }
    __shared__ float s1[256], s2[256];
    s1[tid] = sum; s2[tid] = sq;
    __syncthreads();
    for (int s = 128; s > 0; s >>= 1) {
        if (tid < s) { s1[tid] += s1[tid + s]; s2[tid] += s2[tid + s]; }
        __syncthreads();
    }
    __shared__ float mean_s, inv_s, gam[CPG], bet[CPG];
    if (tid == 0) {
        float mean = s1[0] * (1.0f / GN_N);
        float var  = s2[0] * (1.0f / GN_N) - mean * mean;
        mean_s = mean;
        inv_s  = rsqrtf(var + 1e-5f);
    }
    if (tid < CPG) { gam[tid] = gamma[g * CPG + tid]; bet[tid] = beta[g * CPG + tid]; }
    __syncthreads();
    const float mean = mean_s, inv = inv_s;

    for (int p = tid; p < PIX; p += 256) {
        const float4* ptr = (const float4*)(xb + (size_t)p * C_DIM);
        float4*       op  = (float4*)      (ob + (size_t)p * C_DIM);
        #pragma unroll
        for (int j = 0; j < 4; j++) {
            float4 v = ptr[j];
            v.x = (v.x - mean) * inv * gam[j*4+0] + bet[j*4+0];
            v.y = (v.y - mean) * inv * gam[j*4+1] + bet[j*4+1];
            v.z = (v.z - mean) * inv * gam[j*4+2] + bet[j*4+2];
            v.w = (v.w - mean) * inv * gam[j*4+3] + bet[j*4+3];
            op[j] = v;
        }
    }
}

// ---------------- SGEMM: 128x128 tile, BK=8, 256 threads, 8x8 microtile ----
// C[M,N] = scale * (A[M,K] @ op(B)) [+ bias[N]] [+ res[M,N]]
// TRANS_B=false: B is [K,N] row-major.  TRANS_B=true: B is [N,K] row-major.
// All of M%128, N%128, K%8 are 0 for every call in this problem.
template <bool TRANS_B, bool HAS_BIAS, bool HAS_RES>
__global__ __launch_bounds__(256)
void gemm_kernel(const float* __restrict__ A, const float* __restrict__ B,
                 const float* __restrict__ bias, const float* __restrict__ res,
                 float* __restrict__ C, int M, int N, int K, float scale,
                 size_t strideA, size_t strideB, size_t strideC) {
    A += (size_t)blockIdx.z * strideA;
    B += (size_t)blockIdx.z * strideB;
    C += (size_t)blockIdx.z * strideC;

    const int bm = blockIdx.y * 128;
    const int bn = blockIdx.x * 128;

    __shared__ float As[8][128];
    __shared__ float Bs[8][128];

    const int tid = threadIdx.x;
    const int tx  = tid & 15;   // n-direction, 16 threads
    const int ty  = tid >> 4;   // m-direction, 16 threads
    const int lr  = tid >> 1;        // 0..127 (row for A / NT-B loads)
    const int lc  = (tid & 1) * 4;   // 0 or 4
    const int br  = tid >> 5;        // 0..7  (k-row for NN-B loads)
    const int bc  = (tid & 31) * 4;  // 0..124

    float acc[8][8];
    #pragma unroll
    for (int i = 0; i < 8; i++)
        #pragma unroll
        for (int j = 0; j < 8; j++) acc[i][j] = 0.f;

    for (int k0 = 0; k0 < K; k0 += 8) {
        float4 av = *(const float4*)(A + (size_t)(bm + lr) * K + k0 + lc);
        As[lc+0][lr] = av.x; As[lc+1][lr] = av.y;
        As[lc+2][lr] = av.z; As[lc+3][lr] = av.w;

        if (TRANS_B) {
            float4 bv = *(const float4*)(B + (size_t)(bn + lr) * K + k0 + lc);
            Bs[lc+0][lr] = bv.x; Bs[lc+1][lr] = bv.y;
            Bs[lc+2][lr] = bv.z; Bs[lc+3][lr] = bv.w;
        } else {
            float4 bv = *(const float4*)(B + (size_t)(k0 + br) * N + bn + bc);
            *(float4*)(&Bs[br][bc]) = bv;
        }
        __syncthreads();

        #pragma unroll
        for (int kk = 0; kk < 8; kk++) {
            float4 a0 = *(const float4*)(&As[kk][ty * 8]);
            float4 a1 = *(const float4*)(&As[kk][ty * 8 + 4]);
            float4 b0 = *(const float4*)(&Bs[kk][tx * 8]);
            float4 b1 = *(const float4*)(&Bs[kk][tx * 8 + 4]);
            float a[8] = {a0.x, a0.y, a0.z, a0.w, a1.x, a1.y, a1.z, a1.w};
            float b[8] = {b0.x, b0.y, b0.z, b0.w, b1.x, b1.y, b1.z, b1.w};
            #pragma unroll
            for (int i = 0; i < 8; i++)
                #pragma unroll
                for (int j = 0; j < 8; j++)
                    acc[i][j] += a[i] * b[j];
        }
        __syncthreads();
    }

    float bvals[8];
    if (HAS_BIAS) {
        #pragma unroll
        for (int j = 0; j < 8; j++) bvals[j] = bias[bn + tx * 8 + j];
    }

    #pragma unroll
    for (int i = 0; i < 8; i++) {
        const size_t m = (size_t)(bm + ty * 8 + i);
        float* crow = C + m * N + bn + tx * 8;
        float out[8];
        #pragma unroll
        for (int j = 0; j < 8; j++) {
            float v = acc[i][j] * scale;
            if (HAS_BIAS) v += bvals[j];
            out[j] = v;
        }
        if (HAS_RES) {
            const float* rrow = res + m * N + bn + tx * 8;
            float4 r0 = *(const float4*)(rrow);
            float4 r1 = *(const float4*)(rrow + 4);
            out[0] += r0.x; out[1] += r0.y; out[2] += r0.z; out[3] += r0.w;
            out[4] += r1.x; out[5] += r1.y; out[6] += r1.z; out[7] += r1.w;
        }
        *(float4*)(crow)     = make_float4(out[0], out[1], out[2], out[3]);
        *(float4*)(crow + 4) = make_float4(out[4], out[5], out[6], out[7]);
    }
}

// ---------------- row softmax over 4096 elements, one block per row --------
__global__ void softmax_kernel(float* __restrict__ s) {
    const size_t row = blockIdx.x;
    float4* p = (float4*)(s + row * (size_t)PIX);
    const int tid = threadIdx.x;

    float4 v[4];
    float mx = -1e30f;
    #pragma unroll
    for (int j = 0; j < 4; j++) {
        v[j] = p[tid + 256 * j];
        mx = fmaxf(mx, fmaxf(fmaxf(v[j].x, v[j].y), fmaxf(v[j].z, v[j].w)));
    }
    __shared__ float red[256];
    red[tid] = mx;
    __syncthreads();
    for (int st = 128; st > 0; st >>= 1) {
        if (tid < st) red[tid] = fmaxf(red[tid], red[tid + st]);
        __syncthreads();
    }
    mx = red[0];
    __syncthreads();

    float sum = 0.f;
    #pragma unroll
    for (int j = 0; j < 4; j++) {
        v[j].x = __expf(v[j].x - mx);
        v[j].y = __expf(v[j].y - mx);
        v[j].z = __expf(v[j].z - mx);
        v[j].w = __expf(v[j].w - mx);
        sum += v[j].x + v[j].y + v[j].z + v[j].w;
    }
    red[tid] = sum;
    __syncthreads();
    for (int st = 128; st > 0; st >>= 1) {
        if (tid < st) red[tid] += red[tid + st];
        __syncthreads();
    }
    const float inv = 1.0f / red[0];

    #pragma unroll
    for (int j = 0; j < 4; j++) {
        v[j].x *= inv; v[j].y *= inv; v[j].z *= inv; v[j].w *= inv;
        p[tid + 256 * j] = v[j];
    }
}

// ---------------- launch ----------------------------------------------------
extern "C" void kernel_launch(void* const* d_in, const int* in_sizes, int n_in,
                              void* d_out, int out_size) {
    const float* x     = (const float*)d_in[0];
    const float* gamma = (const float*)d_in[1];
    const float* beta  = (const float*)d_in[2];
    const float* wq    = (const float*)d_in[3];
    const float* bq    = (const float*)d_in[4];
    const float* wk    = (const float*)d_in[5];
    const float* bk    = (const float*)d_in[6];
    const float* wv    = (const float*)d_in[7];
    const float* bv    = (const float*)d_in[8];
    const float* wp    = (const float*)d_in[9];
    const float* bp    = (const float*)d_in[10];
    float* out = (float*)d_out;

    float *xn, *q, *k, *v, *o, *s;
    cudaGetSymbolAddress((void**)&xn, g_xn);
    cudaGetSymbolAddress((void**)&q,  g_q);
    cudaGetSymbolAddress((void**)&k,  g_k);
    cudaGetSymbolAddress((void**)&v,  g_v);
    cudaGetSymbolAddress((void**)&o,  g_o);
    cudaGetSymbolAddress((void**)&s,  g_s);

    const float scale = 0.044194173824159216f;  // 512^-0.5

    // 1) GroupNorm
    groupnorm_kernel<<<BATCH * NGROUP, 256>>>(x, gamma, beta, xn);

    // 2) Q,K,V projections: [8192,512] @ [512,512] + bias
    dim3 gProj(C_DIM / 128, M_TOT / 128, 1);
    gemm_kernel<false, true, false><<<gProj, 256>>>(xn, wq, bq, nullptr, q,
        M_TOT, C_DIM, C_DIM, 1.0f, 0, 0, 0);
    gemm_kernel<false, true, false><<<gProj, 256>>>(xn, wk, bk, nullptr, k,
        M_TOT, C_DIM, C_DIM, 1.0f, 0, 0, 0);
    gemm_kernel<false, true, false><<<gProj, 256>>>(xn, wv, bv, nullptr, v,
        M_TOT, C_DIM, C_DIM, 1.0f, 0, 0, 0);

    // 3) Scores: S = scale * Q @ K^T, per batch  [4096,512]x[4096,512]^T
    dim3 gScore(PIX / 128, PIX / 128, BATCH);
    gemm_kernel<true, false, false><<<gScore, 256>>>(q, k, nullptr, nullptr, s,
        PIX, PIX, C_DIM, scale,
        (size_t)PIX * C_DIM, (size_t)PIX * C_DIM, (size_t)PIX * PIX);

    // 4) Row softmax (in place)
    softmax_kernel<<<BATCH * PIX, 256>>>(s);

    // 5) O = P @ V, per batch  [4096,4096]x[4096,512]
    dim3 gPV(C_DIM / 128, PIX / 128, BATCH);
    gemm_kernel<false, false, false><<<gPV, 256>>>(s, v, nullptr, nullptr, o,
        PIX, C_DIM, PIX, 1.0f,
        (size_t)PIX * PIX, (size_t)PIX * C_DIM, (size_t)PIX * C_DIM);

    // 6) Final projection + bias + residual
    gemm_kernel<false, true, true><<<gProj, 256>>>(o, wp, bp, x, out,
        M_TOT, C_DIM, C_DIM, 1.0f, 0, 0, 0);
}

// round 8
// speedup vs baseline: 2.9760x; 2.9760x over previous
#include <cuda_runtime.h>
#include <math.h>
#include <stdint.h>

#define C_DIM  512
#define PIX    4096          // H*W = 64*64
#define BATCH  2
#define M_TOT  (BATCH * PIX) // 8192
#define NGROUP 32
#define CPG    16            // channels per group
#define GN_N   65536.0f      // PIX * CPG elements per (b,g)

// ---------------- scratch (device globals; no runtime allocation) ----------
__device__ float g_xn[(size_t)M_TOT * C_DIM];
__device__ float g_q [(size_t)M_TOT * C_DIM];
__device__ float g_k [(size_t)M_TOT * C_DIM];
__device__ float g_v [(size_t)M_TOT * C_DIM];
__device__ float g_o [(size_t)M_TOT * C_DIM];
__device__ float g_s [(size_t)BATCH * PIX * PIX];   // attention scores/probs

// ---------------- PTX helpers ----------------------------------------------
__device__ __forceinline__ uint32_t smem_u32(const void* p) {
    return (uint32_t)__cvta_generic_to_shared(p);
}
__device__ __forceinline__ void cp_async16(uint32_t dst, const void* src) {
    asm volatile("cp.async.cg.shared.global [%0], [%1], 16;\n" :: "r"(dst), "l"(src));
}
__device__ __forceinline__ void cp_commit() {
    asm volatile("cp.async.commit_group;\n" ::: "memory");
}
__device__ __forceinline__ void cp_wait1() {
    asm volatile("cp.async.wait_group 1;\n" ::: "memory");
}
__device__ __forceinline__ uint32_t f2tf32(float x) {
    uint32_t r;
    asm("cvt.rna.tf32.f32 %0, %1;" : "=r"(r) : "f"(x));
    return r;
}
__device__ __forceinline__ void mma_tf32(float* c, const uint32_t* a, const uint32_t* b) {
    asm volatile(
        "mma.sync.aligned.m16n8k8.row.col.f32.tf32.tf32.f32 "
        "{%0,%1,%2,%3}, {%4,%5,%6,%7}, {%8,%9}, {%0,%1,%2,%3};\n"
        : "+f"(c[0]), "+f"(c[1]), "+f"(c[2]), "+f"(c[3])
        : "r"(a[0]), "r"(a[1]), "r"(a[2]), "r"(a[3]), "r"(b[0]), "r"(b[1]));
}

// ---------------- GroupNorm: one block per (batch, group) ------------------
__global__ void groupnorm_kernel(const float* __restrict__ x,
                                 const float* __restrict__ gamma,
                                 const float* __restrict__ beta,
                                 float* __restrict__ xn) {
    const int b = blockIdx.x >> 5;
    const int g = blockIdx.x & 31;
    const float* xb = x  + (size_t)b * PIX * C_DIM + g * CPG;
    float*       ob = xn + (size_t)b * PIX * C_DIM + g * CPG;
    const int tid = threadIdx.x;

    float sum = 0.f, sq = 0.f;
    for (int p = tid; p < PIX; p += 256) {
        const float4* ptr = (const float4*)(xb + (size_t)p * C_DIM);
        #pragma unroll
        for (int j = 0; j < 4; j++) {
            float4 v = ptr[j];
            sum += v.x + v.y + v.z + v.w;
            sq  += v.x*v.x + v.y*v.y + v.z*v.z + v.w*v.w;
        }
    }
    __shared__ float s1[256], s2[256];
    s1[tid] = sum; s2[tid] = sq;
    __syncthreads();
    for (int s = 128; s > 0; s >>= 1) {
        if (tid < s) { s1[tid] += s1[tid + s]; s2[tid] += s2[tid + s]; }
        __syncthreads();
    }
    __shared__ float mean_s, inv_s, gam[CPG], bet[CPG];
    if (tid == 0) {
        float mean = s1[0] * (1.0f / GN_N);
        float var  = s2[0] * (1.0f / GN_N) - mean * mean;
        mean_s = mean;
        inv_s  = rsqrtf(var + 1e-5f);
    }
    if (tid < CPG) { gam[tid] = gamma[g * CPG + tid]; bet[tid] = beta[g * CPG + tid]; }
    __syncthreads();
    const float mean = mean_s, inv = inv_s;

    for (int p = tid; p < PIX; p += 256) {
        const float4* ptr = (const float4*)(xb + (size_t)p * C_DIM);
        float4*       op  = (float4*)      (ob + (size_t)p * C_DIM);
        #pragma unroll
        for (int j = 0; j < 4; j++) {
            float4 v = ptr[j];
            v.x = (v.x - mean) * inv * gam[j*4+0] + bet[j*4+0];
            v.y = (v.y - mean) * inv * gam[j*4+1] + bet[j*4+1];
            v.z = (v.z - mean) * inv * gam[j*4+2] + bet[j*4+2];
            v.w = (v.w - mean) * inv * gam[j*4+3] + bet[j*4+3];
            op[j] = v;
        }
    }
}

// ---------------- TF32 tensor-core GEMM ------------------------------------
// C[M,N] = scale * (A[M,K] @ op(B)) [+ bias[N]] [+ res[M,N]]
// TRANS_B=false: B is [K,N] row-major.  TRANS_B=true: B is [N,K] row-major.
// Tile: 128x128, BK=16. 256 threads = 8 warps (4 in M x 2 in N),
// warp tile 32x64 = 2x8 m16n8k8 mma tiles. 2-stage cp.async pipeline.
// Bank-conflict-free smem: A row stride 20 (20m mod 32 permutes, +k fills),
// NN B row stride 136 (8k+n covers all banks), NT B uses A-style layout.
template <bool TRANS_B, bool HAS_BIAS, bool HAS_RES>
__global__ __launch_bounds__(256)
void gemm_tc(const float* __restrict__ A, const float* __restrict__ B,
             const float* __restrict__ bias, const float* __restrict__ res,
             float* __restrict__ C, int M, int N, int K, float scale,
             size_t strideA, size_t strideB, size_t strideC) {
    A += (size_t)blockIdx.z * strideA;
    B += (size_t)blockIdx.z * strideB;
    C += (size_t)blockIdx.z * strideC;

    const int bm = blockIdx.y * 128;
    const int bn = blockIdx.x * 128;

    constexpr int ASTR  = 20;                    // floats per A smem row
    constexpr int BROWS = TRANS_B ? 128 : 16;
    constexpr int BSTR  = TRANS_B ? 20  : 136;
    constexpr int ASZ   = 128 * ASTR;
    constexpr int BSZ   = BROWS * BSTR;

    __shared__ float As[2 * ASZ];
    __shared__ float Bs[2 * BSZ];

    const int tid  = threadIdx.x;
    const int lane = tid & 31;
    const int warp = tid >> 5;
    const int wm   = warp >> 1;     // 0..3
    const int wn   = warp & 1;      // 0..1
    const int g    = lane >> 2;     // groupID 0..7
    const int tg   = lane & 3;      // thread-in-group 0..3

    // global-load coordinates (2 x 16B chunks per thread per tile per matrix)
    const int am0 = tid >> 2;               // 0..63
    const int akc = (tid & 3) * 4;          // 0,4,8,12
    const int bkr = tid >> 5;               // 0..7   (NN)
    const int bnc = (tid & 31) * 4;         // 0..124 (NN)

    float acc[2][8][4];
    #pragma unroll
    for (int i = 0; i < 2; i++)
        #pragma unroll
        for (int j = 0; j < 8; j++)
            #pragma unroll
            for (int l = 0; l < 4; l++) acc[i][j][l] = 0.f;

    const int nT = K >> 4;  // K / 16

    // ---- tile loader ----
    auto loadTile = [&](int it, int buf) {
        const int k0 = it << 4;
        float* ab = As + buf * ASZ;
        float* bb = Bs + buf * BSZ;
        #pragma unroll
        for (int i = 0; i < 2; i++) {
            int m = am0 + 64 * i;
            cp_async16(smem_u32(ab + m * ASTR + akc),
                       A + (size_t)(bm + m) * K + k0 + akc);
        }
        if (TRANS_B) {
            #pragma unroll
            for (int i = 0; i < 2; i++) {
                int n = am0 + 64 * i;
                cp_async16(smem_u32(bb + n * BSTR + akc),
                           B + (size_t)(bn + n) * K + k0 + akc);
            }
        } else {
            #pragma unroll
            for (int i = 0; i < 2; i++) {
                int kr = bkr + 8 * i;
                cp_async16(smem_u32(bb + kr * BSTR + bnc),
                           B + (size_t)(k0 + kr) * N + bn + bnc);
            }
        }
    };

    // ---- prologue ----
    loadTile(0, 0); cp_commit();
    loadTile(1, 1); cp_commit();
    cp_wait1();
    __syncthreads();

    // ---- main loop ----
    for (int it = 0; it < nT; it++) {
        const int cur = it & 1;
        const float* ab = As + cur * ASZ;
        const float* bb = Bs + cur * BSZ;

        #pragma unroll
        for (int ks = 0; ks < 2; ks++) {
            const int kb = ks * 8;
            uint32_t af[2][4];
            #pragma unroll
            for (int mt = 0; mt < 2; mt++) {
                const int r = wm * 32 + mt * 16 + g;
                af[mt][0] = f2tf32(ab[(r    ) * ASTR + kb + tg    ]);
                af[mt][1] = f2tf32(ab[(r + 8) * ASTR + kb + tg    ]);
                af[mt][2] = f2tf32(ab[(r    ) * ASTR + kb + tg + 4]);
                af[mt][3] = f2tf32(ab[(r + 8) * ASTR + kb + tg + 4]);
            }
            uint32_t bf[8][2];
            #pragma unroll
            for (int nt = 0; nt < 8; nt++) {
                const int cidx = wn * 64 + nt * 8 + g;
                if (TRANS_B) {
                    bf[nt][0] = f2tf32(bb[cidx * BSTR + kb + tg    ]);
                    bf[nt][1] = f2tf32(bb[cidx * BSTR + kb + tg + 4]);
                } else {
                    bf[nt][0] = f2tf32(bb[(kb + tg    ) * BSTR + cidx]);
                    bf[nt][1] = f2tf32(bb[(kb + tg + 4) * BSTR + cidx]);
                }
            }
            #pragma unroll
            for (int mt = 0; mt < 2; mt++)
                #pragma unroll
                for (int nt = 0; nt < 8; nt++)
                    mma_tf32(acc[mt][nt], af[mt], bf[nt]);
        }

        __syncthreads();
        if (it + 2 < nT) loadTile(it + 2, cur);
        cp_commit();
        cp_wait1();
        __syncthreads();
    }

    // ---- epilogue: scale, bias, residual, store ----
    #pragma unroll
    for (int mt = 0; mt < 2; mt++) {
        const int row0 = bm + wm * 32 + mt * 16 + g;
        #pragma unroll
        for (int nt = 0; nt < 8; nt++) {
            const int col = bn + wn * 64 + nt * 8 + tg * 2;
            float o0 = acc[mt][nt][0] * scale;
            float o1 = acc[mt][nt][1] * scale;
            float o2 = acc[mt][nt][2] * scale;
            float o3 = acc[mt][nt][3] * scale;
            if (HAS_BIAS) {
                float2 bv = *(const float2*)(bias + col);
                o0 += bv.x; o1 += bv.y; o2 += bv.x; o3 += bv.y;
            }
            if (HAS_RES) {
                float2 r0 = *(const float2*)(res + (size_t)row0 * N + col);
                float2 r1 = *(const float2*)(res + (size_t)(row0 + 8) * N + col);
                o0 += r0.x; o1 += r0.y; o2 += r1.x; o3 += r1.y;
            }
            *(float2*)(C + (size_t)row0 * N + col)       = make_float2(o0, o1);
            *(float2*)(C + (size_t)(row0 + 8) * N + col) = make_float2(o2, o3);
        }
    }
}

// ---------------- row softmax over 4096 elements, one block per row --------
__global__ void softmax_kernel(float* __restrict__ s) {
    const size_t row = blockIdx.x;
    float4* p = (float4*)(s + row * (size_t)PIX);
    const int tid = threadIdx.x;

    float4 v[4];
    float mx = -1e30f;
    #pragma unroll
    for (int j = 0; j < 4; j++) {
        v[j] = p[tid + 256 * j];
        mx = fmaxf(mx, fmaxf(fmaxf(v[j].x, v[j].y), fmaxf(v[j].z, v[j].w)));
    }
    __shared__ float red[256];
    red[tid] = mx;
    __syncthreads();
    for (int st = 128; st > 0; st >>= 1) {
        if (tid < st) red[tid] = fmaxf(red[tid], red[tid + st]);
        __syncthreads();
    }
    mx = red[0];
    __syncthreads();

    float sum = 0.f;
    #pragma unroll
    for (int j = 0; j < 4; j++) {
        v[j].x = __expf(v[j].x - mx);
        v[j].y = __expf(v[j].y - mx);
        v[j].z = __expf(v[j].z - mx);
        v[j].w = __expf(v[j].w - mx);
        sum += v[j].x + v[j].y + v[j].z + v[j].w;
    }
    red[tid] = sum;
    __syncthreads();
    for (int st = 128; st > 0; st >>= 1) {
        if (tid < st) red[tid] += red[tid + st];
        __syncthreads();
    }
    const float inv = 1.0f / red[0];

    #pragma unroll
    for (int j = 0; j < 4; j++) {
        v[j].x *= inv; v[j].y *= inv; v[j].z *= inv; v[j].w *= inv;
        p[tid + 256 * j] = v[j];
    }
}

// ---------------- launch ----------------------------------------------------
extern "C" void kernel_launch(void* const* d_in, const int* in_sizes, int n_in,
                              void* d_out, int out_size) {
    const float* x     = (const float*)d_in[0];
    const float* gamma = (const float*)d_in[1];
    const float* beta  = (const float*)d_in[2];
    const float* wq    = (const float*)d_in[3];
    const float* bq    = (const float*)d_in[4];
    const float* wk    = (const float*)d_in[5];
    const float* bk    = (const float*)d_in[6];
    const float* wv    = (const float*)d_in[7];
    const float* bv    = (const float*)d_in[8];
    const float* wp    = (const float*)d_in[9];
    const float* bp    = (const float*)d_in[10];
    float* out = (float*)d_out;

    float *xn, *q, *k, *v, *o, *s;
    cudaGetSymbolAddress((void**)&xn, g_xn);
    cudaGetSymbolAddress((void**)&q,  g_q);
    cudaGetSymbolAddress((void**)&k,  g_k);
    cudaGetSymbolAddress((void**)&v,  g_v);
    cudaGetSymbolAddress((void**)&o,  g_o);
    cudaGetSymbolAddress((void**)&s,  g_s);

    const float scale = 0.044194173824159216f;  // 512^-0.5

    // 1) GroupNorm
    groupnorm_kernel<<<BATCH * NGROUP, 256>>>(x, gamma, beta, xn);

    // 2) Q,K,V projections: [8192,512] @ [512,512] + bias
    dim3 gProj(C_DIM / 128, M_TOT / 128, 1);
    gemm_tc<false, true, false><<<gProj, 256>>>(xn, wq, bq, nullptr, q,
        M_TOT, C_DIM, C_DIM, 1.0f, 0, 0, 0);
    gemm_tc<false, true, false><<<gProj, 256>>>(xn, wk, bk, nullptr, k,
        M_TOT, C_DIM, C_DIM, 1.0f, 0, 0, 0);
    gemm_tc<false, true, false><<<gProj, 256>>>(xn, wv, bv, nullptr, v,
        M_TOT, C_DIM, C_DIM, 1.0f, 0, 0, 0);

    // 3) Scores: S = scale * Q @ K^T, per batch  [4096,512]x[4096,512]^T
    dim3 gScore(PIX / 128, PIX / 128, BATCH);
    gemm_tc<true, false, false><<<gScore, 256>>>(q, k, nullptr, nullptr, s,
        PIX, PIX, C_DIM, scale,
        (size_t)PIX * C_DIM, (size_t)PIX * C_DIM, (size_t)PIX * PIX);

    // 4) Row softmax (in place)
    softmax_kernel<<<BATCH * PIX, 256>>>(s);

    // 5) O = P @ V, per batch  [4096,4096]x[4096,512]
    dim3 gPV(C_DIM / 128, PIX / 128, BATCH);
    gemm_tc<false, false, false><<<gPV, 256>>>(s, v, nullptr, nullptr, o,
        PIX, C_DIM, PIX, 1.0f,
        (size_t)PIX * PIX, (size_t)PIX * C_DIM, (size_t)PIX * C_DIM);

    // 6) Final projection + bias + residual
    gemm_tc<false, true, true><<<gProj, 256>>>(o, wp, bp, x, out,
        M_TOT, C_DIM, C_DIM, 1.0f, 0, 0, 0);
}

// round 11
// speedup vs baseline: 5.2194x; 1.7538x over previous
#include <cuda_runtime.h>
#include <cuda_bf16.h>
#include <math.h>
#include <stdint.h>

#define C_DIM  512
#define PIX    4096          // H*W = 64*64
#define BATCH  2
#define M_TOT  (BATCH * PIX) // 8192
#define NGROUP 32
#define CPG    16            // channels per group
#define GN_N   65536.0f      // PIX * CPG elements per (b,g)

// ---------------- scratch (device globals; no runtime allocation) ----------
__device__ __nv_bfloat16 g_xn[(size_t)M_TOT * C_DIM];
__device__ __nv_bfloat16 g_q [(size_t)M_TOT * C_DIM];
__device__ __nv_bfloat16 g_k [(size_t)M_TOT * C_DIM];
__device__ __nv_bfloat16 g_v [(size_t)M_TOT * C_DIM];
__device__ __nv_bfloat16 g_vT[(size_t)C_DIM * M_TOT];   // [C][B*PIX]
__device__ __nv_bfloat16 g_o [(size_t)M_TOT * C_DIM];
__device__ __nv_bfloat16 g_s [(size_t)BATCH * PIX * PIX]; // scores/probs
__device__ __nv_bfloat16 g_wt[4][(size_t)C_DIM * C_DIM];  // transposed bf16 weights

// ---------------- PTX helpers ----------------------------------------------
__device__ __forceinline__ uint32_t smem_u32(const void* p) {
    return (uint32_t)__cvta_generic_to_shared(p);
}
__device__ __forceinline__ void cp_async16(uint32_t dst, const void* src) {
    asm volatile("cp.async.cg.shared.global [%0], [%1], 16;\n" :: "r"(dst), "l"(src));
}
__device__ __forceinline__ void cp_commit() {
    asm volatile("cp.async.commit_group;\n" ::: "memory");
}
__device__ __forceinline__ void cp_wait1() {
    asm volatile("cp.async.wait_group 1;\n" ::: "memory");
}
__device__ __forceinline__ void mma_bf16(float* c, const uint32_t* a, const uint32_t* b) {
    asm volatile(
        "mma.sync.aligned.m16n8k16.row.col.f32.bf16.bf16.f32 "
        "{%0,%1,%2,%3}, {%4,%5,%6,%7}, {%8,%9}, {%0,%1,%2,%3};\n"
        : "+f"(c[0]), "+f"(c[1]), "+f"(c[2]), "+f"(c[3])
        : "r"(a[0]), "r"(a[1]), "r"(a[2]), "r"(a[3]), "r"(b[0]), "r"(b[1]));
}

// ---------------- GroupNorm: one block per (batch, group), bf16 out --------
__global__ void groupnorm_kernel(const float* __restrict__ x,
                                 const float* __restrict__ gamma,
                                 const float* __restrict__ beta,
                                 __nv_bfloat16* __restrict__ xn) {
    const int b = blockIdx.x >> 5;
    const int g = blockIdx.x & 31;
    const float*   xb = x  + (size_t)b * PIX * C_DIM + g * CPG;
    __nv_bfloat16* ob = xn + (size_t)b * PIX * C_DIM + g * CPG;
    const int tid = threadIdx.x;

    float sum = 0.f, sq = 0.f;
    for (int p = tid; p < PIX; p += 256) {
        const float4* ptr = (const float4*)(xb + (size_t)p * C_DIM);
        #pragma unroll
        for (int j = 0; j < 4; j++) {
            float4 v = ptr[j];
            sum += v.x + v.y + v.z + v.w;
            sq  += v.x*v.x + v.y*v.y + v.z*v.z + v.w*v.w;
        }
    }
    __shared__ float s1[256], s2[256];
    s1[tid] = sum; s2[tid] = sq;
    __syncthreads();
    for (int s = 128; s > 0; s >>= 1) {
        if (tid < s) { s1[tid] += s1[tid + s]; s2[tid] += s2[tid + s]; }
        __syncthreads();
    }
    __shared__ float mean_s, inv_s, gam[CPG], bet[CPG];
    if (tid == 0) {
        float mean = s1[0] * (1.0f / GN_N);
        float var  = s2[0] * (1.0f / GN_N) - mean * mean;
        mean_s = mean;
        inv_s  = rsqrtf(var + 1e-5f);
    }
    if (tid < CPG) { gam[tid] = gamma[g * CPG + tid]; bet[tid] = beta[g * CPG + tid]; }
    __syncthreads();
    const float mean = mean_s, inv = inv_s;

    for (int p = tid; p < PIX; p += 256) {
        const float4* ptr = (const float4*)(xb + (size_t)p * C_DIM);
        __nv_bfloat162 hh[8];
        #pragma unroll
        for (int j = 0; j < 4; j++) {
            float4 v = ptr[j];
            float o0 = (v.x - mean) * inv * gam[j*4+0] + bet[j*4+0];
            float o1 = (v.y - mean) * inv * gam[j*4+1] + bet[j*4+1];
            float o2 = (v.z - mean) * inv * gam[j*4+2] + bet[j*4+2];
            float o3 = (v.w - mean) * inv * gam[j*4+3] + bet[j*4+3];
            hh[j*2+0] = __float22bfloat162_rn(make_float2(o0, o1));
            hh[j*2+1] = __float22bfloat162_rn(make_float2(o2, o3));
        }
        uint4* dst = (uint4*)(ob + (size_t)p * C_DIM);
        const uint4* src = (const uint4*)hh;
        dst[0] = src[0];
        dst[1] = src[1];
    }
}

// -------- weight convert+transpose: w[512][512] f32 -> wT[512][512] bf16 ----
__global__ void wtrans_kernel(const float* __restrict__ w0, const float* __restrict__ w1,
                              const float* __restrict__ w2, const float* __restrict__ w3,
                              __nv_bfloat16* __restrict__ o0, __nv_bfloat16* __restrict__ o1,
                              __nv_bfloat16* __restrict__ o2, __nv_bfloat16* __restrict__ o3) {
    const float* w = (blockIdx.z == 0) ? w0 : (blockIdx.z == 1) ? w1 : (blockIdx.z == 2) ? w2 : w3;
    __nv_bfloat16* o = (blockIdx.z == 0) ? o0 : (blockIdx.z == 1) ? o1 : (blockIdx.z == 2) ? o2 : o3;
    __shared__ float t[32][33];
    const int tx = threadIdx.x, ty = threadIdx.y;
    const int x = blockIdx.x * 32 + tx;
    const int y = blockIdx.y * 32 + ty;
    #pragma unroll
    for (int j = 0; j < 4; j++)
        t[ty + 8*j][tx] = w[(size_t)(y + 8*j) * C_DIM + x];
    __syncthreads();
    const int x2 = blockIdx.y * 32 + tx;
    const int y2 = blockIdx.x * 32 + ty;
    #pragma unroll
    for (int j = 0; j < 4; j++)
        o[(size_t)(y2 + 8*j) * C_DIM + x2] = __float2bfloat16(t[tx][ty + 8*j]);
}

// -------- v transpose: v[8192][512] bf16 -> vT[512][8192] bf16 --------------
__global__ void vtrans_kernel(const __nv_bfloat16* __restrict__ v,
                              __nv_bfloat16* __restrict__ vT) {
    __shared__ __nv_bfloat16 t[32][33];
    const int tx = threadIdx.x, ty = threadIdx.y;
    const int x = blockIdx.x * 32 + tx;   // channel
    const int y = blockIdx.y * 32 + ty;   // token
    #pragma unroll
    for (int j = 0; j < 4; j++)
        t[ty + 8*j][tx] = v[(size_t)(y + 8*j) * C_DIM + x];
    __syncthreads();
    const int x2 = blockIdx.y * 32 + tx;  // token
    const int y2 = blockIdx.x * 32 + ty;  // channel
    #pragma unroll
    for (int j = 0; j < 4; j++)
        vT[(size_t)(y2 + 8*j) * M_TOT + x2] = t[tx][ty + 8*j];
}

// ---------------- BF16 tensor-core GEMM (NT: both operands K-major) --------
// C[M,N] = scale * (A[M,K] @ B[N,K]^T) [+ bias[N]] [+ res[M,N]]
// Tile 128x128, BK=32. 8 warps (4m x 2n), warp tile 32x64 = 2x8 m16n8k16.
// Smem rows: 32 bf16 = 16 words, padded to stride 20 words -> (20g+tg) mod 32
// covers all banks: conflict-free LDS.32 fragment loads, no cvt in mainloop.
template <bool HAS_BIAS, bool HAS_RES, bool OUT_BF16>
__global__ __launch_bounds__(256)
void gemm_bf16(const __nv_bfloat16* __restrict__ A, const __nv_bfloat16* __restrict__ B,
               const float* __restrict__ bias, const float* __restrict__ res,
               void* __restrict__ Cout, int M, int N, int K,
               int lda, int ldb, int ldc, float scale,
               size_t strideA, size_t strideB, size_t strideC) {
    A += (size_t)blockIdx.z * strideA;
    B += (size_t)blockIdx.z * strideB;

    const int bm = blockIdx.y * 128;
    const int bn = blockIdx.x * 128;

    constexpr int WSTR = 20;              // words (bf16x2) per smem row
    constexpr int TSZ  = 128 * WSTR;      // words per tile

    __shared__ uint32_t As[2][TSZ];
    __shared__ uint32_t Bs[2][TSZ];

    const int tid  = threadIdx.x;
    const int lane = tid & 31;
    const int warp = tid >> 5;
    const int wm   = warp >> 1;     // 0..3
    const int wn   = warp & 1;      // 0..1
    const int g    = lane >> 2;     // 0..7
    const int tg   = lane & 3;      // 0..3

    float acc[2][8][4];
    #pragma unroll
    for (int i = 0; i < 2; i++)
        #pragma unroll
        for (int j = 0; j < 8; j++)
            #pragma unroll
            for (int l = 0; l < 4; l++) acc[i][j][l] = 0.f;

    const int nT = K >> 5;   // K / 32

    auto loadTile = [&](int it, int buf) {
        const int k0 = it << 5;
        uint32_t* ab = As[buf];
        uint32_t* bb = Bs[buf];
        #pragma unroll
        for (int i = 0; i < 2; i++) {
            const int idx = tid + 256 * i;
            const int m = idx >> 2;        // 0..127
            const int c = idx & 3;         // 16B chunk (8 bf16)
            cp_async16(smem_u32(ab + m * WSTR + c * 4),
                       A + (size_t)(bm + m) * lda + k0 + c * 8);
            cp_async16(smem_u32(bb + m * WSTR + c * 4),
                       B + (size_t)(bn + m) * ldb + k0 + c * 8);
        }
    };

    // ---- prologue ----
    loadTile(0, 0); cp_commit();
    loadTile(1, 1); cp_commit();
    cp_wait1();
    __syncthreads();

    // ---- main loop ----
    for (int it = 0; it < nT; it++) {
        const int cur = it & 1;
        const uint32_t* ab = As[cur];
        const uint32_t* bb = Bs[cur];

        #pragma unroll
        for (int ks = 0; ks < 2; ks++) {
            const int kb = ks * 8;
            uint32_t af[2][4];
            #pragma unroll
            for (int mt = 0; mt < 2; mt++) {
                const int w = (wm * 32 + mt * 16 + g) * WSTR + kb + tg;
                af[mt][0] = ab[w];
                af[mt][1] = ab[w + 8 * WSTR];
                af[mt][2] = ab[w + 4];
                af[mt][3] = ab[w + 8 * WSTR + 4];
            }
            uint32_t bf[8][2];
            #pragma unroll
            for (int nt = 0; nt < 8; nt++) {
                const int w = (wn * 64 + nt * 8 + g) * WSTR + kb + tg;
                bf[nt][0] = bb[w];
                bf[nt][1] = bb[w + 4];
            }
            #pragma unroll
            for (int mt = 0; mt < 2; mt++)
                #pragma unroll
                for (int nt = 0; nt < 8; nt++)
                    mma_bf16(acc[mt][nt], af[mt], bf[nt]);
        }

        __syncthreads();
        if (it + 2 < nT) loadTile(it + 2, cur);
        cp_commit();
        cp_wait1();
        __syncthreads();
    }

    // ---- epilogue ----
    #pragma unroll
    for (int mt = 0; mt < 2; mt++) {
        const int row0 = bm + wm * 32 + mt * 16 + g;
        #pragma unroll
        for (int nt = 0; nt < 8; nt++) {
            const int col = bn + wn * 64 + nt * 8 + tg * 2;
            float o0 = acc[mt][nt][0] * scale;
            float o1 = acc[mt][nt][1] * scale;
            float o2 = acc[mt][nt][2] * scale;
            float o3 = acc[mt][nt][3] * scale;
            if (HAS_BIAS) {
                float2 bv = *(const float2*)(bias + col);
                o0 += bv.x; o1 += bv.y; o2 += bv.x; o3 += bv.y;
            }
            if (HAS_RES) {
                float2 r0 = *(const float2*)(res + (size_t)row0 * ldc + col);
                float2 r1 = *(const float2*)(res + (size_t)(row0 + 8) * ldc + col);
                o0 += r0.x; o1 += r0.y; o2 += r1.x; o3 += r1.y;
            }
            if (OUT_BF16) {
                __nv_bfloat16* C = (__nv_bfloat16*)Cout + (size_t)blockIdx.z * strideC;
                *(__nv_bfloat162*)(C + (size_t)row0 * ldc + col) =
                    __float22bfloat162_rn(make_float2(o0, o1));
                *(__nv_bfloat162*)(C + (size_t)(row0 + 8) * ldc + col) =
                    __float22bfloat162_rn(make_float2(o2, o3));
            } else {
                float* C = (float*)Cout + (size_t)blockIdx.z * strideC;
                *(float2*)(C + (size_t)row0 * ldc + col)       = make_float2(o0, o1);
                *(float2*)(C + (size_t)(row0 + 8) * ldc + col) = make_float2(o2, o3);
            }
        }
    }
}

// ---------------- row softmax over 4096 bf16, one block per row ------------
__global__ void softmax_kernel(__nv_bfloat16* __restrict__ s) {
    const size_t row = blockIdx.x;
    uint4* p = (uint4*)(s + row * (size_t)PIX);   // 512 uint4 per row
    const int tid = threadIdx.x;

    uint4 u[2];
    float f[16];
    #pragma unroll
    for (int j = 0; j < 2; j++) u[j] = p[tid + 256 * j];
    #pragma unroll
    for (int j = 0; j < 2; j++) {
        const uint32_t* w = (const uint32_t*)&u[j];
        #pragma unroll
        for (int q = 0; q < 4; q++) {
            float2 fv = __bfloat1622float2(*(const __nv_bfloat162*)&w[q]);
            f[j*8 + q*2 + 0] = fv.x;
            f[j*8 + q*2 + 1] = fv.y;
        }
    }

    float mx = -1e30f;
    #pragma unroll
    for (int i = 0; i < 16; i++) mx = fmaxf(mx, f[i]);

    __shared__ float red[256];
    red[tid] = mx;
    __syncthreads();
    for (int st = 128; st > 0; st >>= 1) {
        if (tid < st) red[tid] = fmaxf(red[tid], red[tid + st]);
        __syncthreads();
    }
    mx = red[0];
    __syncthreads();

    float sum = 0.f;
    #pragma unroll
    for (int i = 0; i < 16; i++) { f[i] = __expf(f[i] - mx); sum += f[i]; }
    red[tid] = sum;
    __syncthreads();
    for (int st = 128; st > 0; st >>= 1) {
        if (tid < st) red[tid] += red[tid + st];
        __syncthreads();
    }
    const float inv = 1.0f / red[0];

    #pragma unroll
    for (int j = 0; j < 2; j++) {
        uint32_t* w = (uint32_t*)&u[j];
        #pragma unroll
        for (int q = 0; q < 4; q++) {
            __nv_bfloat162 h = __float22bfloat162_rn(
                make_float2(f[j*8 + q*2] * inv, f[j*8 + q*2 + 1] * inv));
            w[q] = *(const uint32_t*)&h;
        }
        p[tid + 256 * j] = u[j];
    }
}

// ---------------- launch ----------------------------------------------------
extern "C" void kernel_launch(void* const* d_in, const int* in_sizes, int n_in,
                              void* d_out, int out_size) {
    const float* x     = (const float*)d_in[0];
    const float* gamma = (const float*)d_in[1];
    const float* beta  = (const float*)d_in[2];
    const float* wq    = (const float*)d_in[3];
    const float* bq    = (const float*)d_in[4];
    const float* wk    = (const float*)d_in[5];
    const float* bk    = (const float*)d_in[6];
    const float* wv    = (const float*)d_in[7];
    const float* bv    = (const float*)d_in[8];
    const float* wp    = (const float*)d_in[9];
    const float* bp    = (const float*)d_in[10];
    float* out = (float*)d_out;

    __nv_bfloat16 *xn, *q, *k, *v, *vT, *o, *s, *wt;
    cudaGetSymbolAddress((void**)&xn, g_xn);
    cudaGetSymbolAddress((void**)&q,  g_q);
    cudaGetSymbolAddress((void**)&k,  g_k);
    cudaGetSymbolAddress((void**)&v,  g_v);
    cudaGetSymbolAddress((void**)&vT, g_vT);
    cudaGetSymbolAddress((void**)&o,  g_o);
    cudaGetSymbolAddress((void**)&s,  g_s);
    cudaGetSymbolAddress((void**)&wt, g_wt);
    __nv_bfloat16* wqt = wt;
    __nv_bfloat16* wkt = wt + (size_t)C_DIM * C_DIM;
    __nv_bfloat16* wvt = wt + (size_t)2 * C_DIM * C_DIM;
    __nv_bfloat16* wpt = wt + (size_t)3 * C_DIM * C_DIM;

    const float scale = 0.044194173824159216f;  // 512^-0.5

    // 0) weights -> bf16 transposed
    wtrans_kernel<<<dim3(16, 16, 4), dim3(32, 8)>>>(wq, wk, wv, wp, wqt, wkt, wvt, wpt);

    // 1) GroupNorm (bf16 out)
    groupnorm_kernel<<<BATCH * NGROUP, 256>>>(x, gamma, beta, xn);

    // 2) Q,K,V projections: [8192,512] @ wT[512,512]^T + bias -> bf16
    dim3 gProj(C_DIM / 128, M_TOT / 128, 1);
    gemm_bf16<true, false, true><<<gProj, 256>>>(xn, wqt, bq, nullptr, q,
        M_TOT, C_DIM, C_DIM, C_DIM, C_DIM, C_DIM, 1.0f, 0, 0, 0);
    gemm_bf16<true, false, true><<<gProj, 256>>>(xn, wkt, bk, nullptr, k,
        M_TOT, C_DIM, C_DIM, C_DIM, C_DIM, C_DIM, 1.0f, 0, 0, 0);
    gemm_bf16<true, false, true><<<gProj, 256>>>(xn, wvt, bv, nullptr, v,
        M_TOT, C_DIM, C_DIM, C_DIM, C_DIM, C_DIM, 1.0f, 0, 0, 0);

    // 3) v -> vT [512, 8192]
    vtrans_kernel<<<dim3(C_DIM / 32, M_TOT / 32), dim3(32, 8)>>>(v, vT);

    // 4) Scores: S = scale * Q @ K^T per batch (NT, bf16 out)
    dim3 gScore(PIX / 128, PIX / 128, BATCH);
    gemm_bf16<false, false, true><<<gScore, 256>>>(q, k, nullptr, nullptr, s,
        PIX, PIX, C_DIM, C_DIM, C_DIM, PIX, scale,
        (size_t)PIX * C_DIM, (size_t)PIX * C_DIM, (size_t)PIX * PIX);

    // 5) Row softmax (in place, bf16)
    softmax_kernel<<<BATCH * PIX, 256>>>(s);

    // 6) O = P @ V per batch: A=s [4096,4096], B=vT [512, 8192] (NT)
    dim3 gPV(C_DIM / 128, PIX / 128, BATCH);
    gemm_bf16<false, false, true><<<gPV, 256>>>(s, vT, nullptr, nullptr, o,
        PIX, C_DIM, PIX, PIX, M_TOT, C_DIM, 1.0f,
        (size_t)PIX * PIX, (size_t)PIX, (size_t)PIX * C_DIM);

    // 7) Final projection + bias + residual -> fp32 out
    gemm_bf16<true, true, false><<<gProj, 256>>>(o, wpt, bp, x, out,
        M_TOT, C_DIM, C_DIM, C_DIM, C_DIM, C_DIM, 1.0f, 0, 0, 0);
}

// round 15
// speedup vs baseline: 5.4849x; 1.0509x over previous
#include <cuda_runtime.h>
#include <cuda_bf16.h>
#include <math.h>
#include <stdint.h>

#define C_DIM  512
#define PIX    4096          // H*W = 64*64
#define BATCH  2
#define M_TOT  (BATCH * PIX) // 8192
#define NGROUP 32
#define CPG    16            // channels per group
#define GN_N   65536.0f      // PIX * CPG elements per (b,g)

// ---------------- scratch (device globals; no runtime allocation) ----------
__device__ __nv_bfloat16 g_xn[(size_t)M_TOT * C_DIM];
__device__ __nv_bfloat16 g_q [(size_t)M_TOT * C_DIM];
__device__ __nv_bfloat16 g_k [(size_t)M_TOT * C_DIM];
__device__ __nv_bfloat16 g_v [(size_t)M_TOT * C_DIM];
__device__ __nv_bfloat16 g_vT[(size_t)C_DIM * M_TOT];   // [C][B*PIX]
__device__ __nv_bfloat16 g_o [(size_t)M_TOT * C_DIM];
__device__ __nv_bfloat16 g_s [(size_t)BATCH * PIX * PIX]; // scores/probs
__device__ __nv_bfloat16 g_wt[4][(size_t)C_DIM * C_DIM];  // transposed bf16 weights

// ---------------- PTX helpers ----------------------------------------------
__device__ __forceinline__ uint32_t smem_u32(const void* p) {
    return (uint32_t)__cvta_generic_to_shared(p);
}
__device__ __forceinline__ void cp_async16(uint32_t dst, const void* src) {
    asm volatile("cp.async.cg.shared.global [%0], [%1], 16;\n" :: "r"(dst), "l"(src));
}
__device__ __forceinline__ void cp_commit() {
    asm volatile("cp.async.commit_group;\n" ::: "memory");
}
__device__ __forceinline__ void cp_wait2() {
    asm volatile("cp.async.wait_group 2;\n" ::: "memory");
}
__device__ __forceinline__ void mma_bf16(float* c, const uint32_t* a, const uint32_t* b) {
    asm volatile(
        "mma.sync.aligned.m16n8k16.row.col.f32.bf16.bf16.f32 "
        "{%0,%1,%2,%3}, {%4,%5,%6,%7}, {%8,%9}, {%0,%1,%2,%3};\n"
        : "+f"(c[0]), "+f"(c[1]), "+f"(c[2]), "+f"(c[3])
        : "r"(a[0]), "r"(a[1]), "r"(a[2]), "r"(a[3]), "r"(b[0]), "r"(b[1]));
}
#define LDSM4(r0, r1, r2, r3, addr) \
    asm volatile("ldmatrix.sync.aligned.m8n8.x4.shared.b16 {%0,%1,%2,%3}, [%4];" \
        : "=r"(r0), "=r"(r1), "=r"(r2), "=r"(r3) : "r"(addr))

// ---------------- GroupNorm: one block per (batch, group), bf16 out --------
__global__ void groupnorm_kernel(const float* __restrict__ x,
                                 const float* __restrict__ gamma,
                                 const float* __restrict__ beta,
                                 __nv_bfloat16* __restrict__ xn) {
    const int b = blockIdx.x >> 5;
    const int g = blockIdx.x & 31;
    const float*   xb = x  + (size_t)b * PIX * C_DIM + g * CPG;
    __nv_bfloat16* ob = xn + (size_t)b * PIX * C_DIM + g * CPG;
    const int tid = threadIdx.x;

    float sum = 0.f, sq = 0.f;
    for (int p = tid; p < PIX; p += 256) {
        const float4* ptr = (const float4*)(xb + (size_t)p * C_DIM);
        #pragma unroll
        for (int j = 0; j < 4; j++) {
            float4 v = ptr[j];
            sum += v.x + v.y + v.z + v.w;
            sq  += v.x*v.x + v.y*v.y + v.z*v.z + v.w*v.w;
        }
    }
    __shared__ float s1[256], s2[256];
    s1[tid] = sum; s2[tid] = sq;
    __syncthreads();
    for (int s = 128; s > 0; s >>= 1) {
        if (tid < s) { s1[tid] += s1[tid + s]; s2[tid] += s2[tid + s]; }
        __syncthreads();
    }
    __shared__ float mean_s, inv_s, gam[CPG], bet[CPG];
    if (tid == 0) {
        float mean = s1[0] * (1.0f / GN_N);
        float var  = s2[0] * (1.0f / GN_N) - mean * mean;
        mean_s = mean;
        inv_s  = rsqrtf(var + 1e-5f);
    }
    if (tid < CPG) { gam[tid] = gamma[g * CPG + tid]; bet[tid] = beta[g * CPG + tid]; }
    __syncthreads();
    const float mean = mean_s, inv = inv_s;

    for (int p = tid; p < PIX; p += 256) {
        const float4* ptr = (const float4*)(xb + (size_t)p * C_DIM);
        __nv_bfloat162 hh[8];
        #pragma unroll
        for (int j = 0; j < 4; j++) {
            float4 v = ptr[j];
            float o0 = (v.x - mean) * inv * gam[j*4+0] + bet[j*4+0];
            float o1 = (v.y - mean) * inv * gam[j*4+1] + bet[j*4+1];
            float o2 = (v.z - mean) * inv * gam[j*4+2] + bet[j*4+2];
            float o3 = (v.w - mean) * inv * gam[j*4+3] + bet[j*4+3];
            hh[j*2+0] = __float22bfloat162_rn(make_float2(o0, o1));
            hh[j*2+1] = __float22bfloat162_rn(make_float2(o2, o3));
        }
        uint4* dst = (uint4*)(ob + (size_t)p * C_DIM);
        const uint4* src = (const uint4*)hh;
        dst[0] = src[0];
        dst[1] = src[1];
    }
}

// -------- weight convert+transpose: w[512][512] f32 -> wT[512][512] bf16 ----
__global__ void wtrans_kernel(const float* __restrict__ w0, const float* __restrict__ w1,
                              const float* __restrict__ w2, const float* __restrict__ w3,
                              __nv_bfloat16* __restrict__ o0, __nv_bfloat16* __restrict__ o1,
                              __nv_bfloat16* __restrict__ o2, __nv_bfloat16* __restrict__ o3) {
    const float* w = (blockIdx.z == 0) ? w0 : (blockIdx.z == 1) ? w1 : (blockIdx.z == 2) ? w2 : w3;
    __nv_bfloat16* o = (blockIdx.z == 0) ? o0 : (blockIdx.z == 1) ? o1 : (blockIdx.z == 2) ? o2 : o3;
    __shared__ float t[32][33];
    const int tx = threadIdx.x, ty = threadIdx.y;
    const int x = blockIdx.x * 32 + tx;
    const int y = blockIdx.y * 32 + ty;
    #pragma unroll
    for (int j = 0; j < 4; j++)
        t[ty + 8*j][tx] = w[(size_t)(y + 8*j) * C_DIM + x];
    __syncthreads();
    const int x2 = blockIdx.y * 32 + tx;
    const int y2 = blockIdx.x * 32 + ty;
    #pragma unroll
    for (int j = 0; j < 4; j++)
        o[(size_t)(y2 + 8*j) * C_DIM + x2] = __float2bfloat16(t[tx][ty + 8*j]);
}

// -------- v transpose: v[8192][512] bf16 -> vT[512][8192] bf16 --------------
__global__ void vtrans_kernel(const __nv_bfloat16* __restrict__ v,
                              __nv_bfloat16* __restrict__ vT) {
    __shared__ __nv_bfloat16 t[32][33];
    const int tx = threadIdx.x, ty = threadIdx.y;
    const int x = blockIdx.x * 32 + tx;   // channel
    const int y = blockIdx.y * 32 + ty;   // token
    #pragma unroll
    for (int j = 0; j < 4; j++)
        t[ty + 8*j][tx] = v[(size_t)(y + 8*j) * C_DIM + x];
    __syncthreads();
    const int x2 = blockIdx.y * 32 + tx;  // token
    const int y2 = blockIdx.x * 32 + ty;  // channel
    #pragma unroll
    for (int j = 0; j < 4; j++)
        vT[(size_t)(y2 + 8*j) * M_TOT + x2] = t[tx][ty + 8*j];
}

// ---------------- BF16 tensor-core GEMM (NT: both operands K-major) --------
// C[M,N] = scale * (A[M,K] @ B[N,K]^T) [+ bias[N]] [+ res[M,N]]
// Tile 128x128, BK=32, 4-stage cp.async ring (one __syncthreads per stage),
// ldmatrix.x4 fragment loads. 8 warps (4m x 2n), warp tile 32x64.
// Smem rows: 32 bf16 = 16 words padded to 20 -> ldmatrix 8-row phases hit
// word-groups (5r+c) mod 8 = permutation: conflict-free.
#define GSTAGES 4
#define WSTR    20                     // words per smem row
#define TILEW   (128 * WSTR)           // 2560 words per matrix tile
#define STAGEW  (2 * TILEW)            // 5120 words per stage (A + B)
#define GSMEM   (GSTAGES * STAGEW * 4) // 81920 bytes

template <bool HAS_BIAS, bool HAS_RES, bool OUT_BF16>
__global__ __launch_bounds__(256)
void gemm_bf16(const __nv_bfloat16* __restrict__ A, const __nv_bfloat16* __restrict__ B,
               const float* __restrict__ bias, const float* __restrict__ res,
               void* __restrict__ Cout, int K,
               int lda, int ldb, int ldc, float scale,
               size_t strideA, size_t strideB, size_t strideC) {
    extern __shared__ uint32_t smem[];
    A += (size_t)blockIdx.z * strideA;
    B += (size_t)blockIdx.z * strideB;

    const int bm = blockIdx.y * 128;
    const int bn = blockIdx.x * 128;

    const int tid  = threadIdx.x;
    const int lane = tid & 31;
    const int warp = tid >> 5;
    const int wm   = warp >> 1;     // 0..3
    const int wn   = warp & 1;      // 0..1
    const int g    = lane >> 2;     // 0..7
    const int tg   = lane & 3;      // 0..3

    const uint32_t sbase = smem_u32(smem);

    // ldmatrix per-lane word offsets (within a tile)
    // A: groups of 8 lanes -> {rows0-7,k0} {rows8-15,k0} {rows0-7,k8} {rows8-15,k8}
    const int aword = (wm * 32 + (lane & 15)) * WSTR + ((lane >> 4) << 2);
    // B: {n0-7,k0} {n0-7,k8} {n8-15,k0} {n8-15,k8} per 16-wide n pair
    const int bword = (wn * 64 + ((lane >> 4) & 1) * 8 + (lane & 7)) * WSTR
                    + ((lane >> 3) & 1) * 4;

    float acc[2][8][4];
    #pragma unroll
    for (int i = 0; i < 2; i++)
        #pragma unroll
        for (int j = 0; j < 8; j++)
            #pragma unroll
            for (int l = 0; l < 4; l++) acc[i][j][l] = 0.f;

    const int nT = K >> 5;   // K / 32

    auto loadTile = [&](int it, int s) {
        const int k0 = it << 5;
        uint32_t* ab = smem + s * STAGEW;
        uint32_t* bb = ab + TILEW;
        #pragma unroll
        for (int i = 0; i < 2; i++) {
            const int idx = tid + 256 * i;
            const int m = idx >> 2;        // 0..127
            const int c = idx & 3;         // 16B chunk (8 bf16)
            cp_async16(smem_u32(ab + m * WSTR + c * 4),
                       A + (size_t)(bm + m) * lda + k0 + c * 8);
            cp_async16(smem_u32(bb + m * WSTR + c * 4),
                       B + (size_t)(bn + m) * ldb + k0 + c * 8);
        }
    };

    // ---- prologue: stages 0,1,2 in flight ----
    loadTile(0, 0); cp_commit();
    loadTile(1, 1); cp_commit();
    loadTile(2, 2); cp_commit();

    // ---- main loop: one __syncthreads per iteration ----
    for (int it = 0; it < nT; it++) {
        cp_wait2();                        // stage `it` resident
        __syncthreads();                   // everyone done with stage (it-1)%4

        if (it + 3 < nT) loadTile(it + 3, (it + 3) & 3);
        cp_commit();                       // always commit (empty groups ok)

        const uint32_t aoff = sbase + ((it & 3) * STAGEW) * 4;
        const uint32_t boff = aoff + TILEW * 4;

        #pragma unroll
        for (int ks = 0; ks < 2; ks++) {
            uint32_t af[2][4];
            #pragma unroll
            for (int mt = 0; mt < 2; mt++)
                LDSM4(af[mt][0], af[mt][1], af[mt][2], af[mt][3],
                      aoff + (uint32_t)(aword + mt * 16 * WSTR + ks * 8) * 4);
            uint32_t bfm[4][4];
            #pragma unroll
            for (int np = 0; np < 4; np++)
                LDSM4(bfm[np][0], bfm[np][1], bfm[np][2], bfm[np][3],
                      boff + (uint32_t)(bword + np * 16 * WSTR + ks * 8) * 4);
            #pragma unroll
            for (int mt = 0; mt < 2; mt++)
                #pragma unroll
                for (int np = 0; np < 4; np++) {
                    mma_bf16(acc[mt][np*2],     af[mt], &bfm[np][0]);
                    mma_bf16(acc[mt][np*2 + 1], af[mt], &bfm[np][2]);
                }
        }
    }

    // ---- epilogue ----
    #pragma unroll
    for (int mt = 0; mt < 2; mt++) {
        const int row0 = bm + wm * 32 + mt * 16 + g;
        #pragma unroll
        for (int nt = 0; nt < 8; nt++) {
            const int col = bn + wn * 64 + nt * 8 + tg * 2;
            float o0 = acc[mt][nt][0] * scale;
            float o1 = acc[mt][nt][1] * scale;
            float o2 = acc[mt][nt][2] * scale;
            float o3 = acc[mt][nt][3] * scale;
            if (HAS_BIAS) {
                float2 bv = *(const float2*)(bias + col);
                o0 += bv.x; o1 += bv.y; o2 += bv.x; o3 += bv.y;
            }
            if (HAS_RES) {
                float2 r0 = *(const float2*)(res + (size_t)row0 * ldc + col);
                float2 r1 = *(const float2*)(res + (size_t)(row0 + 8) * ldc + col);
                o0 += r0.x; o1 += r0.y; o2 += r1.x; o3 += r1.y;
            }
            if (OUT_BF16) {
                __nv_bfloat16* C = (__nv_bfloat16*)Cout + (size_t)blockIdx.z * strideC;
                *(__nv_bfloat162*)(C + (size_t)row0 * ldc + col) =
                    __float22bfloat162_rn(make_float2(o0, o1));
                *(__nv_bfloat162*)(C + (size_t)(row0 + 8) * ldc + col) =
                    __float22bfloat162_rn(make_float2(o2, o3));
            } else {
                float* C = (float*)Cout + (size_t)blockIdx.z * strideC;
                *(float2*)(C + (size_t)row0 * ldc + col)       = make_float2(o0, o1);
                *(float2*)(C + (size_t)(row0 + 8) * ldc + col) = make_float2(o2, o3);
            }
        }
    }
}

// ---------------- row softmax over 4096 bf16, one block per row ------------
__global__ void softmax_kernel(__nv_bfloat16* __restrict__ s) {
    const size_t row = blockIdx.x;
    uint4* p = (uint4*)(s + row * (size_t)PIX);   // 512 uint4 per row
    const int tid = threadIdx.x;

    uint4 u[2];
    float f[16];
    #pragma unroll
    for (int j = 0; j < 2; j++) u[j] = p[tid + 256 * j];
    #pragma unroll
    for (int j = 0; j < 2; j++) {
        const uint32_t* w = (const uint32_t*)&u[j];
        #pragma unroll
        for (int q = 0; q < 4; q++) {
            float2 fv = __bfloat1622float2(*(const __nv_bfloat162*)&w[q]);
            f[j*8 + q*2 + 0] = fv.x;
            f[j*8 + q*2 + 1] = fv.y;
        }
    }

    float mx = -1e30f;
    #pragma unroll
    for (int i = 0; i < 16; i++) mx = fmaxf(mx, f[i]);

    __shared__ float red[256];
    red[tid] = mx;
    __syncthreads();
    for (int st = 128; st > 0; st >>= 1) {
        if (tid < st) red[tid] = fmaxf(red[tid], red[tid + st]);
        __syncthreads();
    }
    mx = red[0];
    __syncthreads();

    float sum = 0.f;
    #pragma unroll
    for (int i = 0; i < 16; i++) { f[i] = __expf(f[i] - mx); sum += f[i]; }
    red[tid] = sum;
    __syncthreads();
    for (int st = 128; st > 0; st >>= 1) {
        if (tid < st) red[tid] += red[tid + st];
        __syncthreads();
    }
    const float inv = 1.0f / red[0];

    #pragma unroll
    for (int j = 0; j < 2; j++) {
        uint32_t* w = (uint32_t*)&u[j];
        #pragma unroll
        for (int q = 0; q < 4; q++) {
            __nv_bfloat162 h = __float22bfloat162_rn(
                make_float2(f[j*8 + q*2] * inv, f[j*8 + q*2 + 1] * inv));
            w[q] = *(const uint32_t*)&h;
        }
        p[tid + 256 * j] = u[j];
    }
}

// ---------------- launch ----------------------------------------------------
extern "C" void kernel_launch(void* const* d_in, const int* in_sizes, int n_in,
                              void* d_out, int out_size) {
    const float* x     = (const float*)d_in[0];
    const float* gamma = (const float*)d_in[1];
    const float* beta  = (const float*)d_in[2];
    const float* wq    = (const float*)d_in[3];
    const float* bq    = (const float*)d_in[4];
    const float* wk    = (const float*)d_in[5];
    const float* bk    = (const float*)d_in[6];
    const float* wv    = (const float*)d_in[7];
    const float* bv    = (const float*)d_in[8];
    const float* wp    = (const float*)d_in[9];
    const float* bp    = (const float*)d_in[10];
    float* out = (float*)d_out;

    __nv_bfloat16 *xn, *q, *k, *v, *vT, *o, *s, *wt;
    cudaGetSymbolAddress((void**)&xn, g_xn);
    cudaGetSymbolAddress((void**)&q,  g_q);
    cudaGetSymbolAddress((void**)&k,  g_k);
    cudaGetSymbolAddress((void**)&v,  g_v);
    cudaGetSymbolAddress((void**)&vT, g_vT);
    cudaGetSymbolAddress((void**)&o,  g_o);
    cudaGetSymbolAddress((void**)&s,  g_s);
    cudaGetSymbolAddress((void**)&wt, g_wt);
    __nv_bfloat16* wqt = wt;
    __nv_bfloat16* wkt = wt + (size_t)C_DIM * C_DIM;
    __nv_bfloat16* wvt = wt + (size_t)2 * C_DIM * C_DIM;
    __nv_bfloat16* wpt = wt + (size_t)3 * C_DIM * C_DIM;

    const float scale = 0.044194173824159216f;  // 512^-0.5

    cudaFuncSetAttribute(gemm_bf16<true,  false, true >,
                         cudaFuncAttributeMaxDynamicSharedMemorySize, GSMEM);
    cudaFuncSetAttribute(gemm_bf16<false, false, true >,
                         cudaFuncAttributeMaxDynamicSharedMemorySize, GSMEM);
    cudaFuncSetAttribute(gemm_bf16<true,  true,  false>,
                         cudaFuncAttributeMaxDynamicSharedMemorySize, GSMEM);

    // 0) weights -> bf16 transposed
    wtrans_kernel<<<dim3(16, 16, 4), dim3(32, 8)>>>(wq, wk, wv, wp, wqt, wkt, wvt, wpt);

    // 1) GroupNorm (bf16 out)
    groupnorm_kernel<<<BATCH * NGROUP, 256>>>(x, gamma, beta, xn);

    // 2) Q,K,V projections: [8192,512] @ wT[512,512]^T + bias -> bf16
    dim3 gProj(C_DIM / 128, M_TOT / 128, 1);
    gemm_bf16<true, false, true><<<gProj, 256, GSMEM>>>(xn, wqt, bq, nullptr, q,
        C_DIM, C_DIM, C_DIM, C_DIM, 1.0f, 0, 0, 0);
    gemm_bf16<true, false, true><<<gProj, 256, GSMEM>>>(xn, wkt, bk, nullptr, k,
        C_DIM, C_DIM, C_DIM, C_DIM, 1.0f, 0, 0, 0);
    gemm_bf16<true, false, true><<<gProj, 256, GSMEM>>>(xn, wvt, bv, nullptr, v,
        C_DIM, C_DIM, C_DIM, C_DIM, 1.0f, 0, 0, 0);

    // 3) v -> vT [512, 8192]
    vtrans_kernel<<<dim3(C_DIM / 32, M_TOT / 32), dim3(32, 8)>>>(v, vT);

    // 4) Scores: S = scale * Q @ K^T per batch (NT, bf16 out)
    dim3 gScore(PIX / 128, PIX / 128, BATCH);
    gemm_bf16<false, false, true><<<gScore, 256, GSMEM>>>(q, k, nullptr, nullptr, s,
        C_DIM, C_DIM, C_DIM, PIX, scale,
        (size_t)PIX * C_DIM, (size_t)PIX * C_DIM, (size_t)PIX * PIX);

    // 5) Row softmax (in place, bf16)
    softmax_kernel<<<BATCH * PIX, 256>>>(s);

    // 6) O = P @ V per batch: A = s [4096,4096] (lda=PIX), B = vT (ldb=M_TOT)
    dim3 gPV(C_DIM / 128, PIX / 128, BATCH);
    gemm_bf16<false, false, true><<<gPV, 256, GSMEM>>>(s, vT, nullptr, nullptr, o,
        PIX, PIX, M_TOT, C_DIM, 1.0f,
        (size_t)PIX * PIX, (size_t)PIX, (size_t)PIX * C_DIM);

    // 7) Final projection + bias + residual -> fp32 out
    gemm_bf16<true, true, false><<<gProj, 256, GSMEM>>>(o, wpt, bp, x, out,
        C_DIM, C_DIM, C_DIM, C_DIM, 1.0f, 0, 0, 0);
}

// round 16
// speedup vs baseline: 5.5644x; 1.0145x over previous
#include <cuda_runtime.h>
#include <cuda_bf16.h>
#include <math.h>
#include <stdint.h>

#define C_DIM  512
#define PIX    4096          // H*W = 64*64
#define BATCH  2
#define M_TOT  (BATCH * PIX) // 8192
#define NGROUP 32
#define CPG    16            // channels per group
#define GN_N   65536.0f      // PIX * CPG elements per (b,g)
#define QKV_N  1536

// ---------------- scratch (device globals; no runtime allocation) ----------
__device__ __nv_bfloat16 g_xn [(size_t)M_TOT * C_DIM];
__device__ __nv_bfloat16 g_qkv[(size_t)M_TOT * QKV_N];   // packed q|k|v per row
__device__ __nv_bfloat16 g_vT [(size_t)C_DIM * M_TOT];   // [C][B*PIX]
__device__ __nv_bfloat16 g_o  [(size_t)M_TOT * C_DIM];
__device__ __nv_bfloat16 g_s  [(size_t)BATCH * PIX * PIX]; // scores/probs
__device__ __nv_bfloat16 g_wt [4][(size_t)C_DIM * C_DIM];  // transposed bf16 weights
__device__ float         g_bias[QKV_N];                    // packed bq|bk|bv

// ---------------- PTX helpers ----------------------------------------------
__device__ __forceinline__ uint32_t smem_u32(const void* p) {
    return (uint32_t)__cvta_generic_to_shared(p);
}
__device__ __forceinline__ void cp_async16(uint32_t dst, const void* src) {
    asm volatile("cp.async.cg.shared.global [%0], [%1], 16;\n" :: "r"(dst), "l"(src));
}
__device__ __forceinline__ void cp_commit() {
    asm volatile("cp.async.commit_group;\n" ::: "memory");
}
__device__ __forceinline__ void cp_wait2() {
    asm volatile("cp.async.wait_group 2;\n" ::: "memory");
}
__device__ __forceinline__ void mma_bf16(float* c, const uint32_t* a, const uint32_t* b) {
    asm volatile(
        "mma.sync.aligned.m16n8k16.row.col.f32.bf16.bf16.f32 "
        "{%0,%1,%2,%3}, {%4,%5,%6,%7}, {%8,%9}, {%0,%1,%2,%3};\n"
        : "+f"(c[0]), "+f"(c[1]), "+f"(c[2]), "+f"(c[3])
        : "r"(a[0]), "r"(a[1]), "r"(a[2]), "r"(a[3]), "r"(b[0]), "r"(b[1]));
}
#define LDSM4(r0, r1, r2, r3, addr) \
    asm volatile("ldmatrix.sync.aligned.m8n8.x4.shared.b16 {%0,%1,%2,%3}, [%4];" \
        : "=r"(r0), "=r"(r1), "=r"(r2), "=r"(r3) : "r"(addr))

// ---------------- GroupNorm: one block per (batch, group), bf16 out --------
__global__ void groupnorm_kernel(const float* __restrict__ x,
                                 const float* __restrict__ gamma,
                                 const float* __restrict__ beta,
                                 __nv_bfloat16* __restrict__ xn) {
    const int b = blockIdx.x >> 5;
    const int g = blockIdx.x & 31;
    const float*   xb = x  + (size_t)b * PIX * C_DIM + g * CPG;
    __nv_bfloat16* ob = xn + (size_t)b * PIX * C_DIM + g * CPG;
    const int tid = threadIdx.x;

    float sum = 0.f, sq = 0.f;
    for (int p = tid; p < PIX; p += 256) {
        const float4* ptr = (const float4*)(xb + (size_t)p * C_DIM);
        #pragma unroll
        for (int j = 0; j < 4; j++) {
            float4 v = ptr[j];
            sum += v.x + v.y + v.z + v.w;
            sq  += v.x*v.x + v.y*v.y + v.z*v.z + v.w*v.w;
        }
    }
    __shared__ float s1[256], s2[256];
    s1[tid] = sum; s2[tid] = sq;
    __syncthreads();
    for (int s = 128; s > 0; s >>= 1) {
        if (tid < s) { s1[tid] += s1[tid + s]; s2[tid] += s2[tid + s]; }
        __syncthreads();
    }
    __shared__ float mean_s, inv_s, gam[CPG], bet[CPG];
    if (tid == 0) {
        float mean = s1[0] * (1.0f / GN_N);
        float var  = s2[0] * (1.0f / GN_N) - mean * mean;
        mean_s = mean;
        inv_s  = rsqrtf(var + 1e-5f);
    }
    if (tid < CPG) { gam[tid] = gamma[g * CPG + tid]; bet[tid] = beta[g * CPG + tid]; }
    __syncthreads();
    const float mean = mean_s, inv = inv_s;

    for (int p = tid; p < PIX; p += 256) {
        const float4* ptr = (const float4*)(xb + (size_t)p * C_DIM);
        __nv_bfloat162 hh[8];
        #pragma unroll
        for (int j = 0; j < 4; j++) {
            float4 v = ptr[j];
            float o0 = (v.x - mean) * inv * gam[j*4+0] + bet[j*4+0];
            float o1 = (v.y - mean) * inv * gam[j*4+1] + bet[j*4+1];
            float o2 = (v.z - mean) * inv * gam[j*4+2] + bet[j*4+2];
            float o3 = (v.w - mean) * inv * gam[j*4+3] + bet[j*4+3];
            hh[j*2+0] = __float22bfloat162_rn(make_float2(o0, o1));
            hh[j*2+1] = __float22bfloat162_rn(make_float2(o2, o3));
        }
        uint4* dst = (uint4*)(ob + (size_t)p * C_DIM);
        const uint4* src = (const uint4*)hh;
        dst[0] = src[0];
        dst[1] = src[1];
    }
}

// -------- weight convert+transpose: w[512][512] f32 -> wT[512][512] bf16 ----
__global__ void wtrans_kernel(const float* __restrict__ w0, const float* __restrict__ w1,
                              const float* __restrict__ w2, const float* __restrict__ w3,
                              __nv_bfloat16* __restrict__ o0, __nv_bfloat16* __restrict__ o1,
                              __nv_bfloat16* __restrict__ o2, __nv_bfloat16* __restrict__ o3) {
    const float* w = (blockIdx.z == 0) ? w0 : (blockIdx.z == 1) ? w1 : (blockIdx.z == 2) ? w2 : w3;
    __nv_bfloat16* o = (blockIdx.z == 0) ? o0 : (blockIdx.z == 1) ? o1 : (blockIdx.z == 2) ? o2 : o3;
    __shared__ float t[32][33];
    const int tx = threadIdx.x, ty = threadIdx.y;
    const int x = blockIdx.x * 32 + tx;
    const int y = blockIdx.y * 32 + ty;
    #pragma unroll
    for (int j = 0; j < 4; j++)
        t[ty + 8*j][tx] = w[(size_t)(y + 8*j) * C_DIM + x];
    __syncthreads();
    const int x2 = blockIdx.y * 32 + tx;
    const int y2 = blockIdx.x * 32 + ty;
    #pragma unroll
    for (int j = 0; j < 4; j++)
        o[(size_t)(y2 + 8*j) * C_DIM + x2] = __float2bfloat16(t[tx][ty + 8*j]);
}

// -------- bias pack: bq|bk|bv -> g_bias[1536] -------------------------------
__global__ void biaspack_kernel(const float* __restrict__ bq, const float* __restrict__ bk,
                                const float* __restrict__ bv, float* __restrict__ ob) {
    const int i = blockIdx.x * 256 + threadIdx.x;
    ob[i] = (i < 512) ? bq[i] : (i < 1024) ? bk[i - 512] : bv[i - 1024];
}

// -------- v transpose: qkv[:,1024+c] -> vT[512][8192] bf16 ------------------
__global__ void vtrans_kernel(const __nv_bfloat16* __restrict__ qkv,
                              __nv_bfloat16* __restrict__ vT) {
    __shared__ __nv_bfloat16 t[32][33];
    const int tx = threadIdx.x, ty = threadIdx.y;
    const int x = blockIdx.x * 32 + tx;   // channel
    const int y = blockIdx.y * 32 + ty;   // token
    #pragma unroll
    for (int j = 0; j < 4; j++)
        t[ty + 8*j][tx] = qkv[(size_t)(y + 8*j) * QKV_N + 1024 + x];
    __syncthreads();
    const int x2 = blockIdx.y * 32 + tx;  // token
    const int y2 = blockIdx.x * 32 + ty;  // channel
    #pragma unroll
    for (int j = 0; j < 4; j++)
        vT[(size_t)(y2 + 8*j) * M_TOT + x2] = t[tx][ty + 8*j];
}

// ---------------- BF16 tensor-core GEMM (NT: both operands K-major) --------
// C[M,N] = scale * (A[M,K] @ B[N,K]^T) [+ bias[N]] [+ res[M,N]]
// CTA tile 128(M) x 256(N), BK=32, 4-stage cp.async ring, ldmatrix.x4.
// 8 warps in 2(M) x 4(N) grid, warp tile 64x64 (4x8 m16n8 tiles) -> halves
// smem-crossbar fragment traffic per FLOP vs 32x64 warps.
// Smem rows: 32 bf16 = 16 words padded to 20 -> conflict-free ldmatrix.
#define GSTAGES 4
#define WSTR    20                       // words per smem row
#define ATILEW  (128 * WSTR)             // A tile words
#define BTILEW  (256 * WSTR)             // B tile words
#define STAGEW  (ATILEW + BTILEW)        // 7680 words per stage
#define GSMEM   (GSTAGES * STAGEW * 4)   // 122880 bytes

template <bool HAS_BIAS, bool HAS_RES, bool OUT_BF16>
__global__ __launch_bounds__(256, 1)
void gemm_bf16(const __nv_bfloat16* __restrict__ A, const __nv_bfloat16* __restrict__ B,
               const float* __restrict__ bias, const float* __restrict__ res,
               void* __restrict__ Cout, int K,
               int lda, int ldb, int ldc, float scale,
               size_t strideA, size_t strideB, size_t strideC) {
    extern __shared__ uint32_t smem[];
    A += (size_t)blockIdx.z * strideA;
    B += (size_t)blockIdx.z * strideB;

    const int bm = blockIdx.y * 128;
    const int bn = blockIdx.x * 256;

    const int tid  = threadIdx.x;
    const int lane = tid & 31;
    const int warp = tid >> 5;
    const int wm   = warp >> 2;     // 0..1  (M)
    const int wn   = warp & 3;      // 0..3  (N)
    const int g    = lane >> 2;     // 0..7
    const int tg   = lane & 3;      // 0..3

    const uint32_t sbase = smem_u32(smem);

    // ldmatrix per-lane word offsets (within a tile)
    // A (m16k16 frags): quads -> {r0-7,k0}{r8-15,k0}{r0-7,k8}{r8-15,k8}
    const int aword = (wm * 64 + (lane & 15)) * WSTR + ((lane >> 4) << 2);
    // B (n16k16 pair): quads -> {n0-7,k0}{n0-7,k8}{n8-15,k0}{n8-15,k8}
    const int bword = (wn * 64 + ((lane >> 4) & 1) * 8 + (lane & 7)) * WSTR
                    + ((lane >> 3) & 1) * 4;

    float acc[4][8][4];
    #pragma unroll
    for (int i = 0; i < 4; i++)
        #pragma unroll
        for (int j = 0; j < 8; j++)
            #pragma unroll
            for (int l = 0; l < 4; l++) acc[i][j][l] = 0.f;

    const int nT = K >> 5;   // K / 32

    auto loadTile = [&](int it, int s) {
        const int k0 = it << 5;
        uint32_t* ab = smem + s * STAGEW;
        uint32_t* bb = ab + ATILEW;
        #pragma unroll
        for (int i = 0; i < 2; i++) {         // A: 512 chunks
            const int idx = tid + 256 * i;
            const int m = idx >> 2;
            const int c = idx & 3;
            cp_async16(smem_u32(ab + m * WSTR + c * 4),
                       A + (size_t)(bm + m) * lda + k0 + c * 8);
        }
        #pragma unroll
        for (int i = 0; i < 4; i++) {         // B: 1024 chunks
            const int idx = tid + 256 * i;
            const int n = idx >> 2;
            const int c = idx & 3;
            cp_async16(smem_u32(bb + n * WSTR + c * 4),
                       B + (size_t)(bn + n) * ldb + k0 + c * 8);
        }
    };

    // ---- prologue: stages 0,1,2 in flight ----
    loadTile(0, 0); cp_commit();
    loadTile(1, 1); cp_commit();
    loadTile(2, 2); cp_commit();

    // ---- main loop: one __syncthreads per iteration ----
    for (int it = 0; it < nT; it++) {
        cp_wait2();                        // stage `it` resident
        __syncthreads();                   // everyone done with stage (it-1)%4

        if (it + 3 < nT) loadTile(it + 3, (it + 3) & 3);
        cp_commit();                       // always commit (empty groups ok)

        const uint32_t aoff = sbase + ((it & 3) * STAGEW) * 4;
        const uint32_t boff = aoff + ATILEW * 4;

        #pragma unroll
        for (int ks = 0; ks < 2; ks++) {
            uint32_t af[4][4];
            #pragma unroll
            for (int mt = 0; mt < 4; mt++)
                LDSM4(af[mt][0], af[mt][1], af[mt][2], af[mt][3],
                      aoff + (uint32_t)(aword + mt * 16 * WSTR + ks * 8) * 4);
            #pragma unroll
            for (int np = 0; np < 4; np++) {
                uint32_t bf[4];
                LDSM4(bf[0], bf[1], bf[2], bf[3],
                      boff + (uint32_t)(bword + np * 16 * WSTR + ks * 8) * 4);
                #pragma unroll
                for (int mt = 0; mt < 4; mt++) {
                    mma_bf16(acc[mt][np*2],     af[mt], &bf[0]);
                    mma_bf16(acc[mt][np*2 + 1], af[mt], &bf[2]);
                }
            }
        }
    }

    // ---- epilogue ----
    #pragma unroll
    for (int mt = 0; mt < 4; mt++) {
        const int row0 = bm + wm * 64 + mt * 16 + g;
        #pragma unroll
        for (int nt = 0; nt < 8; nt++) {
            const int col = bn + wn * 64 + nt * 8 + tg * 2;
            float o0 = acc[mt][nt][0] * scale;
            float o1 = acc[mt][nt][1] * scale;
            float o2 = acc[mt][nt][2] * scale;
            float o3 = acc[mt][nt][3] * scale;
            if (HAS_BIAS) {
                float2 bv = *(const float2*)(bias + col);
                o0 += bv.x; o1 += bv.y; o2 += bv.x; o3 += bv.y;
            }
            if (HAS_RES) {
                float2 r0 = *(const float2*)(res + (size_t)row0 * ldc + col);
                float2 r1 = *(const float2*)(res + (size_t)(row0 + 8) * ldc + col);
                o0 += r0.x; o1 += r0.y; o2 += r1.x; o3 += r1.y;
            }
            if (OUT_BF16) {
                __nv_bfloat16* C = (__nv_bfloat16*)Cout + (size_t)blockIdx.z * strideC;
                *(__nv_bfloat162*)(C + (size_t)row0 * ldc + col) =
                    __float22bfloat162_rn(make_float2(o0, o1));
                *(__nv_bfloat162*)(C + (size_t)(row0 + 8) * ldc + col) =
                    __float22bfloat162_rn(make_float2(o2, o3));
            } else {
                float* C = (float*)Cout + (size_t)blockIdx.z * strideC;
                *(float2*)(C + (size_t)row0 * ldc + col)       = make_float2(o0, o1);
                *(float2*)(C + (size_t)(row0 + 8) * ldc + col) = make_float2(o2, o3);
            }
        }
    }
}

// ---------------- row softmax over 4096 bf16, one block per row ------------
__global__ void softmax_kernel(__nv_bfloat16* __restrict__ s) {
    const size_t row = blockIdx.x;
    uint4* p = (uint4*)(s + row * (size_t)PIX);   // 512 uint4 per row
    const int tid = threadIdx.x;

    uint4 u[2];
    float f[16];
    #pragma unroll
    for (int j = 0; j < 2; j++) u[j] = p[tid + 256 * j];
    #pragma unroll
    for (int j = 0; j < 2; j++) {
        const uint32_t* w = (const uint32_t*)&u[j];
        #pragma unroll
        for (int q = 0; q < 4; q++) {
            float2 fv = __bfloat1622float2(*(const __nv_bfloat162*)&w[q]);
            f[j*8 + q*2 + 0] = fv.x;
            f[j*8 + q*2 + 1] = fv.y;
        }
    }

    float mx = -1e30f;
    #pragma unroll
    for (int i = 0; i < 16; i++) mx = fmaxf(mx, f[i]);

    __shared__ float red[256];
    red[tid] = mx;
    __syncthreads();
    for (int st = 128; st > 0; st >>= 1) {
        if (tid < st) red[tid] = fmaxf(red[tid], red[tid + st]);
        __syncthreads();
    }
    mx = red[0];
    __syncthreads();

    float sum = 0.f;
    #pragma unroll
    for (int i = 0; i < 16; i++) { f[i] = __expf(f[i] - mx); sum += f[i]; }
    red[tid] = sum;
    __syncthreads();
    for (int st = 128; st > 0; st >>= 1) {
        if (tid < st) red[tid] += red[tid + st];
        __syncthreads();
    }
    const float inv = 1.0f / red[0];

    #pragma unroll
    for (int j = 0; j < 2; j++) {
        uint32_t* w = (uint32_t*)&u[j];
        #pragma unroll
        for (int q = 0; q < 4; q++) {
            __nv_bfloat162 h = __float22bfloat162_rn(
                make_float2(f[j*8 + q*2] * inv, f[j*8 + q*2 + 1] * inv));
            w[q] = *(const uint32_t*)&h;
        }
        p[tid + 256 * j] = u[j];
    }
}

// ---------------- launch ----------------------------------------------------
extern "C" void kernel_launch(void* const* d_in, const int* in_sizes, int n_in,
                              void* d_out, int out_size) {
    const float* x     = (const float*)d_in[0];
    const float* gamma = (const float*)d_in[1];
    const float* beta  = (const float*)d_in[2];
    const float* wq    = (const float*)d_in[3];
    const float* bq    = (const float*)d_in[4];
    const float* wk    = (const float*)d_in[5];
    const float* bk    = (const float*)d_in[6];
    const float* wv    = (const float*)d_in[7];
    const float* bv    = (const float*)d_in[8];
    const float* wp    = (const float*)d_in[9];
    const float* bp    = (const float*)d_in[10];
    float* out = (float*)d_out;

    __nv_bfloat16 *xn, *qkv, *vT, *o, *s, *wt;
    float* bqkv;
    cudaGetSymbolAddress((void**)&xn,   g_xn);
    cudaGetSymbolAddress((void**)&qkv,  g_qkv);
    cudaGetSymbolAddress((void**)&vT,   g_vT);
    cudaGetSymbolAddress((void**)&o,    g_o);
    cudaGetSymbolAddress((void**)&s,    g_s);
    cudaGetSymbolAddress((void**)&wt,   g_wt);
    cudaGetSymbolAddress((void**)&bqkv, g_bias);
    __nv_bfloat16* wqt = wt;                               // [0..3) contiguous
    __nv_bfloat16* wkt = wt + (size_t)C_DIM * C_DIM;
    __nv_bfloat16* wvt = wt + (size_t)2 * C_DIM * C_DIM;
    __nv_bfloat16* wpt = wt + (size_t)3 * C_DIM * C_DIM;

    const float scale = 0.044194173824159216f;  // 512^-0.5

    cudaFuncSetAttribute(gemm_bf16<true,  false, true >,
                         cudaFuncAttributeMaxDynamicSharedMemorySize, GSMEM);
    cudaFuncSetAttribute(gemm_bf16<false, false, true >,
                         cudaFuncAttributeMaxDynamicSharedMemorySize, GSMEM);
    cudaFuncSetAttribute(gemm_bf16<true,  true,  false>,
                         cudaFuncAttributeMaxDynamicSharedMemorySize, GSMEM);

    // 0) weights -> bf16 transposed; biases packed
    wtrans_kernel<<<dim3(16, 16, 4), dim3(32, 8)>>>(wq, wk, wv, wp, wqt, wkt, wvt, wpt);
    biaspack_kernel<<<QKV_N / 256, 256>>>(bq, bk, bv, bqkv);

    // 1) GroupNorm (bf16 out)
    groupnorm_kernel<<<BATCH * NGROUP, 256>>>(x, gamma, beta, xn);

    // 2) Fused QKV projection: [8192,512] @ wqkvT[1536,512]^T + bias -> qkv
    dim3 gQKV(QKV_N / 256, M_TOT / 128, 1);
    gemm_bf16<true, false, true><<<gQKV, 256, GSMEM>>>(xn, wqt, bqkv, nullptr, qkv,
        C_DIM, C_DIM, C_DIM, QKV_N, 1.0f, 0, 0, 0);

    // 3) v -> vT [512, 8192]
    vtrans_kernel<<<dim3(C_DIM / 32, M_TOT / 32), dim3(32, 8)>>>(qkv, vT);

    // 4) Scores: S = scale * Q @ K^T per batch (NT, bf16 out)
    dim3 gScore(PIX / 256, PIX / 128, BATCH);
    gemm_bf16<false, false, true><<<gScore, 256, GSMEM>>>(qkv, qkv + 512, nullptr, nullptr, s,
        C_DIM, QKV_N, QKV_N, PIX, scale,
        (size_t)PIX * QKV_N, (size_t)PIX * QKV_N, (size_t)PIX * PIX);

    // 5) Row softmax (in place, bf16)
    softmax_kernel<<<BATCH * PIX, 256>>>(s);

    // 6) O = P @ V per batch: A = s [4096,4096] (lda=PIX), B = vT (ldb=M_TOT)
    dim3 gPV(C_DIM / 256, PIX / 128, BATCH);
    gemm_bf16<false, false, true><<<gPV, 256, GSMEM>>>(s, vT, nullptr, nullptr, o,
        PIX, PIX, M_TOT, C_DIM, 1.0f,
        (size_t)PIX * PIX, (size_t)PIX, (size_t)PIX * C_DIM);

    // 7) Final projection + bias + residual -> fp32 out
    dim3 gProj(C_DIM / 256, M_TOT / 128, 1);
    gemm_bf16<true, true, false><<<gProj, 256, GSMEM>>>(o, wpt, bp, x, out,
        C_DIM, C_DIM, C_DIM, C_DIM, 1.0f, 0, 0, 0);
}

// round 17
// speedup vs baseline: 6.6233x; 1.1903x over previous
#include <cuda_runtime.h>
#include <cuda_bf16.h>
#include <math.h>
#include <stdint.h>

#define C_DIM  512
#define PIX    4096          // H*W = 64*64
#define BATCH  2
#define M_TOT  (BATCH * PIX) // 8192
#define NGROUP 32
#define CPG    16            // channels per group
#define GN_N   65536.0f      // PIX * CPG elements per (b,g)
#define QKV_N  1536

// ---------------- scratch (device globals; no runtime allocation) ----------
__device__ __nv_bfloat16 g_xn [(size_t)M_TOT * C_DIM];
__device__ __nv_bfloat16 g_qkv[(size_t)M_TOT * QKV_N];   // packed q|k|v per row
__device__ __nv_bfloat16 g_vT [(size_t)C_DIM * M_TOT];   // [C][B*PIX]
__device__ __nv_bfloat16 g_o  [(size_t)M_TOT * C_DIM];
__device__ __nv_bfloat16 g_s  [(size_t)BATCH * PIX * PIX]; // scores/probs
__device__ __nv_bfloat16 g_wt [4][(size_t)C_DIM * C_DIM];  // transposed bf16 weights
__device__ float         g_bias[QKV_N];                    // packed bq|bk|bv

// ---------------- PTX helpers ----------------------------------------------
__device__ __forceinline__ uint32_t smem_u32(const void* p) {
    return (uint32_t)__cvta_generic_to_shared(p);
}
__device__ __forceinline__ void cp_async16(uint32_t dst, const void* src) {
    asm volatile("cp.async.cg.shared.global [%0], [%1], 16;\n" :: "r"(dst), "l"(src));
}
__device__ __forceinline__ void cp_commit() {
    asm volatile("cp.async.commit_group;\n" ::: "memory");
}
__device__ __forceinline__ void cp_wait2() {
    asm volatile("cp.async.wait_group 2;\n" ::: "memory");
}
__device__ __forceinline__ void mma_bf16(float* c, const uint32_t* a, const uint32_t* b) {
    asm volatile(
        "mma.sync.aligned.m16n8k16.row.col.f32.bf16.bf16.f32 "
        "{%0,%1,%2,%3}, {%4,%5,%6,%7}, {%8,%9}, {%0,%1,%2,%3};\n"
        : "+f"(c[0]), "+f"(c[1]), "+f"(c[2]), "+f"(c[3])
        : "r"(a[0]), "r"(a[1]), "r"(a[2]), "r"(a[3]), "r"(b[0]), "r"(b[1]));
}
#define LDSM4(r0, r1, r2, r3, addr) \
    asm volatile("ldmatrix.sync.aligned.m8n8.x4.shared.b16 {%0,%1,%2,%3}, [%4];" \
        : "=r"(r0), "=r"(r1), "=r"(r2), "=r"(r3) : "r"(addr))

// ---------------- GroupNorm: one block per (batch, group), bf16 out --------
__global__ void groupnorm_kernel(const float* __restrict__ x,
                                 const float* __restrict__ gamma,
                                 const float* __restrict__ beta,
                                 __nv_bfloat16* __restrict__ xn) {
    const int b = blockIdx.x >> 5;
    const int g = blockIdx.x & 31;
    const float*   xb = x  + (size_t)b * PIX * C_DIM + g * CPG;
    __nv_bfloat16* ob = xn + (size_t)b * PIX * C_DIM + g * CPG;
    const int tid = threadIdx.x;

    float sum = 0.f, sq = 0.f;
    for (int p = tid; p < PIX; p += 256) {
        const float4* ptr = (const float4*)(xb + (size_t)p * C_DIM);
        #pragma unroll
        for (int j = 0; j < 4; j++) {
            float4 v = ptr[j];
            sum += v.x + v.y + v.z + v.w;
            sq  += v.x*v.x + v.y*v.y + v.z*v.z + v.w*v.w;
        }
    }
    __shared__ float s1[256], s2[256];
    s1[tid] = sum; s2[tid] = sq;
    __syncthreads();
    for (int s = 128; s > 0; s >>= 1) {
        if (tid < s) { s1[tid] += s1[tid + s]; s2[tid] += s2[tid + s]; }
        __syncthreads();
    }
    __shared__ float mean_s, inv_s, gam[CPG], bet[CPG];
    if (tid == 0) {
        float mean = s1[0] * (1.0f / GN_N);
        float var  = s2[0] * (1.0f / GN_N) - mean * mean;
        mean_s = mean;
        inv_s  = rsqrtf(var + 1e-5f);
    }
    if (tid < CPG) { gam[tid] = gamma[g * CPG + tid]; bet[tid] = beta[g * CPG + tid]; }
    __syncthreads();
    const float mean = mean_s, inv = inv_s;

    for (int p = tid; p < PIX; p += 256) {
        const float4* ptr = (const float4*)(xb + (size_t)p * C_DIM);
        __nv_bfloat162 hh[8];
        #pragma unroll
        for (int j = 0; j < 4; j++) {
            float4 v = ptr[j];
            float o0 = (v.x - mean) * inv * gam[j*4+0] + bet[j*4+0];
            float o1 = (v.y - mean) * inv * gam[j*4+1] + bet[j*4+1];
            float o2 = (v.z - mean) * inv * gam[j*4+2] + bet[j*4+2];
            float o3 = (v.w - mean) * inv * gam[j*4+3] + bet[j*4+3];
            hh[j*2+0] = __float22bfloat162_rn(make_float2(o0, o1));
            hh[j*2+1] = __float22bfloat162_rn(make_float2(o2, o3));
        }
        uint4* dst = (uint4*)(ob + (size_t)p * C_DIM);
        const uint4* src = (const uint4*)hh;
        dst[0] = src[0];
        dst[1] = src[1];
    }
}

// -------- weight convert+transpose: w[512][512] f32 -> wT[512][512] bf16 ----
__global__ void wtrans_kernel(const float* __restrict__ w0, const float* __restrict__ w1,
                              const float* __restrict__ w2, const float* __restrict__ w3,
                              __nv_bfloat16* __restrict__ o0, __nv_bfloat16* __restrict__ o1,
                              __nv_bfloat16* __restrict__ o2, __nv_bfloat16* __restrict__ o3) {
    const float* w = (blockIdx.z == 0) ? w0 : (blockIdx.z == 1) ? w1 : (blockIdx.z == 2) ? w2 : w3;
    __nv_bfloat16* o = (blockIdx.z == 0) ? o0 : (blockIdx.z == 1) ? o1 : (blockIdx.z == 2) ? o2 : o3;
    __shared__ float t[32][33];
    const int tx = threadIdx.x, ty = threadIdx.y;
    const int x = blockIdx.x * 32 + tx;
    const int y = blockIdx.y * 32 + ty;
    #pragma unroll
    for (int j = 0; j < 4; j++)
        t[ty + 8*j][tx] = w[(size_t)(y + 8*j) * C_DIM + x];
    __syncthreads();
    const int x2 = blockIdx.y * 32 + tx;
    const int y2 = blockIdx.x * 32 + ty;
    #pragma unroll
    for (int j = 0; j < 4; j++)
        o[(size_t)(y2 + 8*j) * C_DIM + x2] = __float2bfloat16(t[tx][ty + 8*j]);
}

// -------- bias pack: bq|bk|bv -> g_bias[1536] -------------------------------
__global__ void biaspack_kernel(const float* __restrict__ bq, const float* __restrict__ bk,
                                const float* __restrict__ bv, float* __restrict__ ob) {
    const int i = blockIdx.x * 256 + threadIdx.x;
    ob[i] = (i < 512) ? bq[i] : (i < 1024) ? bk[i - 512] : bv[i - 1024];
}

// -------- v transpose: qkv[:,1024+c] -> vT[512][8192] bf16 ------------------
__global__ void vtrans_kernel(const __nv_bfloat16* __restrict__ qkv,
                              __nv_bfloat16* __restrict__ vT) {
    __shared__ __nv_bfloat16 t[32][33];
    const int tx = threadIdx.x, ty = threadIdx.y;
    const int x = blockIdx.x * 32 + tx;   // channel
    const int y = blockIdx.y * 32 + ty;   // token
    #pragma unroll
    for (int j = 0; j < 4; j++)
        t[ty + 8*j][tx] = qkv[(size_t)(y + 8*j) * QKV_N + 1024 + x];
    __syncthreads();
    const int x2 = blockIdx.y * 32 + tx;  // token
    const int y2 = blockIdx.x * 32 + ty;  // channel
    #pragma unroll
    for (int j = 0; j < 4; j++)
        vT[(size_t)(y2 + 8*j) * M_TOT + x2] = t[tx][ty + 8*j];
}

// ---------------- BF16 tensor-core GEMM (NT: both operands K-major) --------
// C[M,N] = scale * (A[M,K] @ B[N,K]^T) [+ bias[N]] [+ res[M,N]]
// CTA tile 128(M) x 128(N), BK=32, 4-stage cp.async ring, ldmatrix.x4.
// 4 warps (2x2) of 64x64 each, 128 threads -> low fragment traffic per FLOP
// AND 2 CTAs/SM (regs 128*208*2 = 53K, smem 80KB*2 = 160KB) so two
// independent CTAs hide each other's sync/latency bubbles.
// Smem rows: 32 bf16 = 16 words padded to 20 -> conflict-free ldmatrix.
#define GSTAGES 4
#define WSTR    20                       // words per smem row
#define ATILEW  (128 * WSTR)             // A tile words
#define BTILEW  (128 * WSTR)             // B tile words
#define STAGEW  (ATILEW + BTILEW)        // 5120 words per stage
#define GSMEM   (GSTAGES * STAGEW * 4)   // 81920 bytes

template <bool HAS_BIAS, bool HAS_RES, bool OUT_BF16>
__global__ __launch_bounds__(128, 2)
void gemm_bf16(const __nv_bfloat16* __restrict__ A, const __nv_bfloat16* __restrict__ B,
               const float* __restrict__ bias, const float* __restrict__ res,
               void* __restrict__ Cout, int K,
               int lda, int ldb, int ldc, float scale,
               size_t strideA, size_t strideB, size_t strideC) {
    extern __shared__ uint32_t smem[];
    A += (size_t)blockIdx.z * strideA;
    B += (size_t)blockIdx.z * strideB;

    const int bm = blockIdx.y * 128;
    const int bn = blockIdx.x * 128;

    const int tid  = threadIdx.x;
    const int lane = tid & 31;
    const int warp = tid >> 5;
    const int wm   = warp >> 1;     // 0..1  (M)
    const int wn   = warp & 1;      // 0..1  (N)
    const int g    = lane >> 2;     // 0..7
    const int tg   = lane & 3;      // 0..3

    const uint32_t sbase = smem_u32(smem);

    // ldmatrix per-lane word offsets (within a tile)
    // A (m16k16 frags): quads -> {r0-7,k0}{r8-15,k0}{r0-7,k8}{r8-15,k8}
    const int aword = (wm * 64 + (lane & 15)) * WSTR + ((lane >> 4) << 2);
    // B (n16k16 pair): quads -> {n0-7,k0}{n0-7,k8}{n8-15,k0}{n8-15,k8}
    const int bword = (wn * 64 + ((lane >> 4) & 1) * 8 + (lane & 7)) * WSTR
                    + ((lane >> 3) & 1) * 4;

    float acc[4][8][4];
    #pragma unroll
    for (int i = 0; i < 4; i++)
        #pragma unroll
        for (int j = 0; j < 8; j++)
            #pragma unroll
            for (int l = 0; l < 4; l++) acc[i][j][l] = 0.f;

    const int nT = K >> 5;   // K / 32

    auto loadTile = [&](int it, int s) {
        const int k0 = it << 5;
        uint32_t* ab = smem + s * STAGEW;
        uint32_t* bb = ab + ATILEW;
        #pragma unroll
        for (int i = 0; i < 4; i++) {         // A: 512 chunks / 128 threads
            const int idx = tid + 128 * i;
            const int m = idx >> 2;
            const int c = idx & 3;
            cp_async16(smem_u32(ab + m * WSTR + c * 4),
                       A + (size_t)(bm + m) * lda + k0 + c * 8);
        }
        #pragma unroll
        for (int i = 0; i < 4; i++) {         // B: 512 chunks / 128 threads
            const int idx = tid + 128 * i;
            const int n = idx >> 2;
            const int c = idx & 3;
            cp_async16(smem_u32(bb + n * WSTR + c * 4),
                       B + (size_t)(bn + n) * ldb + k0 + c * 8);
        }
    };

    // ---- prologue: stages 0,1,2 in flight ----
    loadTile(0, 0); cp_commit();
    loadTile(1, 1); cp_commit();
    loadTile(2, 2); cp_commit();

    // ---- main loop: one __syncthreads per iteration ----
    for (int it = 0; it < nT; it++) {
        cp_wait2();                        // stage `it` resident
        __syncthreads();                   // everyone done with stage (it-1)%4

        if (it + 3 < nT) loadTile(it + 3, (it + 3) & 3);
        cp_commit();                       // always commit (empty groups ok)

        const uint32_t aoff = sbase + ((it & 3) * STAGEW) * 4;
        const uint32_t boff = aoff + ATILEW * 4;

        #pragma unroll
        for (int ks = 0; ks < 2; ks++) {
            uint32_t af[4][4];
            #pragma unroll
            for (int mt = 0; mt < 4; mt++)
                LDSM4(af[mt][0], af[mt][1], af[mt][2], af[mt][3],
                      aoff + (uint32_t)(aword + mt * 16 * WSTR + ks * 8) * 4);
            #pragma unroll
            for (int np = 0; np < 4; np++) {
                uint32_t bf[4];
                LDSM4(bf[0], bf[1], bf[2], bf[3],
                      boff + (uint32_t)(bword + np * 16 * WSTR + ks * 8) * 4);
                #pragma unroll
                for (int mt = 0; mt < 4; mt++) {
                    mma_bf16(acc[mt][np*2],     af[mt], &bf[0]);
                    mma_bf16(acc[mt][np*2 + 1], af[mt], &bf[2]);
                }
            }
        }
    }

    // ---- epilogue ----
    #pragma unroll
    for (int mt = 0; mt < 4; mt++) {
        const int row0 = bm + wm * 64 + mt * 16 + g;
        #pragma unroll
        for (int nt = 0; nt < 8; nt++) {
            const int col = bn + wn * 64 + nt * 8 + tg * 2;
            float o0 = acc[mt][nt][0] * scale;
            float o1 = acc[mt][nt][1] * scale;
            float o2 = acc[mt][nt][2] * scale;
            float o3 = acc[mt][nt][3] * scale;
            if (HAS_BIAS) {
                float2 bv = *(const float2*)(bias + col);
                o0 += bv.x; o1 += bv.y; o2 += bv.x; o3 += bv.y;
            }
            if (HAS_RES) {
                float2 r0 = *(const float2*)(res + (size_t)row0 * ldc + col);
                float2 r1 = *(const float2*)(res + (size_t)(row0 + 8) * ldc + col);
                o0 += r0.x; o1 += r0.y; o2 += r1.x; o3 += r1.y;
            }
            if (OUT_BF16) {
                __nv_bfloat16* C = (__nv_bfloat16*)Cout + (size_t)blockIdx.z * strideC;
                *(__nv_bfloat162*)(C + (size_t)row0 * ldc + col) =
                    __float22bfloat162_rn(make_float2(o0, o1));
                *(__nv_bfloat162*)(C + (size_t)(row0 + 8) * ldc + col) =
                    __float22bfloat162_rn(make_float2(o2, o3));
            } else {
                float* C = (float*)Cout + (size_t)blockIdx.z * strideC;
                *(float2*)(C + (size_t)row0 * ldc + col)       = make_float2(o0, o1);
                *(float2*)(C + (size_t)(row0 + 8) * ldc + col) = make_float2(o2, o3);
            }
        }
    }
}

// ---------------- row softmax over 4096 bf16, one block per row ------------
__global__ void softmax_kernel(__nv_bfloat16* __restrict__ s) {
    const size_t row = blockIdx.x;
    uint4* p = (uint4*)(s + row * (size_t)PIX);   // 512 uint4 per row
    const int tid = threadIdx.x;

    uint4 u[2];
    float f[16];
    #pragma unroll
    for (int j = 0; j < 2; j++) u[j] = p[tid + 256 * j];
    #pragma unroll
    for (int j = 0; j < 2; j++) {
        const uint32_t* w = (const uint32_t*)&u[j];
        #pragma unroll
        for (int q = 0; q < 4; q++) {
            float2 fv = __bfloat1622float2(*(const __nv_bfloat162*)&w[q]);
            f[j*8 + q*2 + 0] = fv.x;
            f[j*8 + q*2 + 1] = fv.y;
        }
    }

    float mx = -1e30f;
    #pragma unroll
    for (int i = 0; i < 16; i++) mx = fmaxf(mx, f[i]);

    __shared__ float red[256];
    red[tid] = mx;
    __syncthreads();
    for (int st = 128; st > 0; st >>= 1) {
        if (tid < st) red[tid] = fmaxf(red[tid], red[tid + st]);
        __syncthreads();
    }
    mx = red[0];
    __syncthreads();

    float sum = 0.f;
    #pragma unroll
    for (int i = 0; i < 16; i++) { f[i] = __expf(f[i] - mx); sum += f[i]; }
    red[tid] = sum;
    __syncthreads();
    for (int st = 128; st > 0; st >>= 1) {
        if (tid < st) red[tid] += red[tid + st];
        __syncthreads();
    }
    const float inv = 1.0f / red[0];

    #pragma unroll
    for (int j = 0; j < 2; j++) {
        uint32_t* w = (uint32_t*)&u[j];
        #pragma unroll
        for (int q = 0; q < 4; q++) {
            __nv_bfloat162 h = __float22bfloat162_rn(
                make_float2(f[j*8 + q*2] * inv, f[j*8 + q*2 + 1] * inv));
            w[q] = *(const uint32_t*)&h;
        }
        p[tid + 256 * j] = u[j];
    }
}

// ---------------- launch ----------------------------------------------------
extern "C" void kernel_launch(void* const* d_in, const int* in_sizes, int n_in,
                              void* d_out, int out_size) {
    const float* x     = (const float*)d_in[0];
    const float* gamma = (const float*)d_in[1];
    const float* beta  = (const float*)d_in[2];
    const float* wq    = (const float*)d_in[3];
    const float* bq    = (const float*)d_in[4];
    const float* wk    = (const float*)d_in[5];
    const float* bk    = (const float*)d_in[6];
    const float* wv    = (const float*)d_in[7];
    const float* bv    = (const float*)d_in[8];
    const float* wp    = (const float*)d_in[9];
    const float* bp    = (const float*)d_in[10];
    float* out = (float*)d_out;

    __nv_bfloat16 *xn, *qkv, *vT, *o, *s, *wt;
    float* bqkv;
    cudaGetSymbolAddress((void**)&xn,   g_xn);
    cudaGetSymbolAddress((void**)&qkv,  g_qkv);
    cudaGetSymbolAddress((void**)&vT,   g_vT);
    cudaGetSymbolAddress((void**)&o,    g_o);
    cudaGetSymbolAddress((void**)&s,    g_s);
    cudaGetSymbolAddress((void**)&wt,   g_wt);
    cudaGetSymbolAddress((void**)&bqkv, g_bias);
    __nv_bfloat16* wqt = wt;                               // [0..3) contiguous
    __nv_bfloat16* wpt = wt + (size_t)3 * C_DIM * C_DIM;
    __nv_bfloat16* wkt = wt + (size_t)C_DIM * C_DIM;
    __nv_bfloat16* wvt = wt + (size_t)2 * C_DIM * C_DIM;

    const float scale = 0.044194173824159216f;  // 512^-0.5

    cudaFuncSetAttribute(gemm_bf16<true,  false, true >,
                         cudaFuncAttributeMaxDynamicSharedMemorySize, GSMEM);
    cudaFuncSetAttribute(gemm_bf16<false, false, true >,
                         cudaFuncAttributeMaxDynamicSharedMemorySize, GSMEM);
    cudaFuncSetAttribute(gemm_bf16<true,  true,  false>,
                         cudaFuncAttributeMaxDynamicSharedMemorySize, GSMEM);

    // 0) weights -> bf16 transposed; biases packed
    wtrans_kernel<<<dim3(16, 16, 4), dim3(32, 8)>>>(wq, wk, wv, wp, wqt, wkt, wvt, wpt);
    biaspack_kernel<<<QKV_N / 256, 256>>>(bq, bk, bv, bqkv);

    // 1) GroupNorm (bf16 out)
    groupnorm_kernel<<<BATCH * NGROUP, 256>>>(x, gamma, beta, xn);

    // 2) Fused QKV projection: [8192,512] @ wqkvT[1536,512]^T + bias -> qkv
    dim3 gQKV(QKV_N / 128, M_TOT / 128, 1);
    gemm_bf16<true, false, true><<<gQKV, 128, GSMEM>>>(xn, wqt, bqkv, nullptr, qkv,
        C_DIM, C_DIM, C_DIM, QKV_N, 1.0f, 0, 0, 0);

    // 3) v -> vT [512, 8192]
    vtrans_kernel<<<dim3(C_DIM / 32, M_TOT / 32), dim3(32, 8)>>>(qkv, vT);

    // 4) Scores: S = scale * Q @ K^T per batch (NT, bf16 out)
    dim3 gScore(PIX / 128, PIX / 128, BATCH);
    gemm_bf16<false, false, true><<<gScore, 128, GSMEM>>>(qkv, qkv + 512, nullptr, nullptr, s,
        C_DIM, QKV_N, QKV_N, PIX, scale,
        (size_t)PIX * QKV_N, (size_t)PIX * QKV_N, (size_t)PIX * PIX);

    // 5) Row softmax (in place, bf16)
    softmax_kernel<<<BATCH * PIX, 256>>>(s);

    // 6) O = P @ V per batch: A = s [4096,4096] (lda=PIX), B = vT (ldb=M_TOT)
    dim3 gPV(C_DIM / 128, PIX / 128, BATCH);
    gemm_bf16<false, false, true><<<gPV, 128, GSMEM>>>(s, vT, nullptr, nullptr, o,
        PIX, PIX, M_TOT, C_DIM, 1.0f,
        (size_t)PIX * PIX, (size_t)PIX, (size_t)PIX * C_DIM);

    // 7) Final projection + bias + residual -> fp32 out
    dim3 gProj(C_DIM / 128, M_TOT / 128, 1);
    gemm_bf16<true, true, false><<<gProj, 128, GSMEM>>>(o, wpt, bp, x, out,
        C_DIM, C_DIM, C_DIM, C_DIM, 1.0f, 0, 0, 0);
}